// round 12
// baseline (speedup 1.0000x reference)
#include <cuda_runtime.h>
#include <cuda_bf16.h>
#include <cstdint>
#include <math.h>

#define STEPS 511
#define BATCH 8
#define HID   256
#define G4    1024
#define VOCAB 32000
#define NROWS (STEPS*BATCH)   // 4088
#define NPAD  4096
#define KCAT  768             // [hi | hi/lo split] concat K
#define WIH_STRIDE 129
#define WIH_BYTES (256*WIH_STRIDE*4)   // 132096

// ---------------- scratch (no allocs allowed) ----------------
__device__ float g_xp[STEPS*BATCH*G4];                // xp0, gate-interleaved [r][unit*4+gate]
__device__ float g_h2[STEPS*BATCH*HID];
__device__ __nv_bfloat16 g_wcat[(size_t)VOCAB*KCAT];  // 49 MB  out_w split
__device__ __nv_bfloat16 g_acat[(size_t)NPAD*KCAT];   // 6.3 MB gated-h2 split

__device__ __forceinline__ float sigmoidf_(float x){ return 1.0f/(1.0f + __expf(-x)); }

__device__ __forceinline__ uint32_t smem_u32(const void* p){
  return (uint32_t)__cvta_generic_to_shared(p);
}
__device__ __forceinline__ void mbar_init_(uint32_t a, uint32_t cnt){
  asm volatile("mbarrier.init.shared.b64 [%0], %1;" :: "r"(a), "r"(cnt) : "memory");
}
__device__ __forceinline__ void mbar_expect_tx_(uint32_t a, uint32_t bytes){
  asm volatile("mbarrier.arrive.expect_tx.shared.b64 _, [%0], %1;" :: "r"(a), "r"(bytes) : "memory");
}
__device__ __forceinline__ void mbar_wait_(uint32_t a, uint32_t phase){
  asm volatile("{\n\t.reg .pred P;\n\t"
    "WL_%=:\n\t"
    "mbarrier.try_wait.parity.acquire.cta.shared::cta.b64 P, [%0], %1, 0x989680;\n\t"
    "@P bra.uni WD_%=;\n\t"
    "bra.uni WL_%=;\n\t"
    "WD_%=:\n\t}" :: "r"(a), "r"(phase) : "memory");
}
__device__ __forceinline__ void st_async_b32_(uint32_t saddr, uint32_t smbar, uint32_t rank, uint32_t v){
  asm volatile("{\n\t.reg .b32 ra, rb;\n\t"
    "mapa.shared::cluster.u32 ra, %0, %2;\n\t"
    "mapa.shared::cluster.u32 rb, %1, %2;\n\t"
    "st.async.shared::cluster.mbarrier::complete_tx::bytes.b32 [ra], %3, [rb];\n\t}"
    :: "r"(saddr), "r"(smbar), "r"(rank), "r"(v) : "memory");
}
__device__ __forceinline__ void mbar_arrive_remote_(uint32_t addr, uint32_t rank){
  asm volatile("{\n\t.reg .b32 ra;\n\t"
    "mapa.shared::cluster.u32 ra, %0, %1;\n\t"
    "mbarrier.arrive.shared::cluster.b64 _, [ra];\n\t}"
    :: "r"(addr), "r"(rank) : "memory");
}
__device__ __forceinline__ void cluster_sync_(){
  asm volatile("barrier.cluster.arrive.aligned;" ::: "memory");
  asm volatile("barrier.cluster.wait.aligned;"   ::: "memory");
}
__device__ __forceinline__ void cp_async16_(uint32_t saddr, const void* gaddr){
  asm volatile("cp.async.cg.shared.global [%0], [%1], 16;" :: "r"(saddr), "l"(gaddr) : "memory");
}
#define CP_COMMIT() asm volatile("cp.async.commit_group;" ::: "memory")
#define CP_WAIT1()  asm volatile("cp.async.wait_group 1;" ::: "memory")
#define CP_WAIT0()  asm volatile("cp.async.wait_group 0;" ::: "memory")

__device__ __forceinline__ void ldsm_x4_(uint32_t* r, uint32_t addr){
  asm volatile("ldmatrix.sync.aligned.m8n8.x4.shared.b16 {%0,%1,%2,%3}, [%4];"
    : "=r"(r[0]), "=r"(r[1]), "=r"(r[2]), "=r"(r[3]) : "r"(addr));
}
__device__ __forceinline__ void mma16816_(float* d, const uint32_t* a, const uint32_t* b){
  asm volatile("mma.sync.aligned.m16n8k16.row.col.f32.bf16.bf16.f32 "
    "{%0,%1,%2,%3}, {%4,%5,%6,%7}, {%8,%9}, {%0,%1,%2,%3};"
    : "+f"(d[0]), "+f"(d[1]), "+f"(d[2]), "+f"(d[3])
    : "r"(a[0]), "r"(a[1]), "r"(a[2]), "r"(a[3]), "r"(b[0]), "r"(b[1]));
}
static __device__ __forceinline__ uint32_t sw128_(uint32_t b){ return b ^ ((b >> 3) & 0x70u); }

// ============================================================
// Layer-0 input projection (K=128), gate-interleaved (proven)
// ============================================================
__global__ void __launch_bounds__(256) xp0_kernel(
    const int* __restrict__ captions, const float* __restrict__ emb_w,
    const float* __restrict__ W, const float* __restrict__ bias1,
    const float* __restrict__ bias2)
{
  __shared__ __align__(16) float As[8][128];
  const int tid = threadIdx.x;
  const int r0  = blockIdx.x * 8;

  for (int idx = tid; idx < 8*128; idx += 256) {
    int row = idx >> 7, k = idx & 127;
    int r = r0 + row;
    int b = r & 7, t = r >> 3;
    As[row][k] = emb_w[(size_t)captions[b*512 + t] * 128 + k];
  }
  __syncthreads();

  float acc[4][8];
  #pragma unroll
  for (int i=0;i<4;i++)
    #pragma unroll
    for (int r=0;r<8;r++) acc[i][r]=0.f;

  const int c0 = tid;
  for (int k0 = 0; k0 < 128; k0 += 4) {
    float4 w0 = *(const float4*)&W[(size_t)(c0      )*128 + k0];
    float4 w1 = *(const float4*)&W[(size_t)(c0+256)*128 + k0];
    float4 w2 = *(const float4*)&W[(size_t)(c0+512)*128 + k0];
    float4 w3 = *(const float4*)&W[(size_t)(c0+768)*128 + k0];
    #pragma unroll
    for (int r=0;r<8;r++) {
      float4 a4 = *(const float4*)&As[r][k0];
      acc[0][r] = fmaf(w0.x, a4.x, acc[0][r]); acc[0][r] = fmaf(w0.y, a4.y, acc[0][r]);
      acc[0][r] = fmaf(w0.z, a4.z, acc[0][r]); acc[0][r] = fmaf(w0.w, a4.w, acc[0][r]);
      acc[1][r] = fmaf(w1.x, a4.x, acc[1][r]); acc[1][r] = fmaf(w1.y, a4.y, acc[1][r]);
      acc[1][r] = fmaf(w1.z, a4.z, acc[1][r]); acc[1][r] = fmaf(w1.w, a4.w, acc[1][r]);
      acc[2][r] = fmaf(w2.x, a4.x, acc[2][r]); acc[2][r] = fmaf(w2.y, a4.y, acc[2][r]);
      acc[2][r] = fmaf(w2.z, a4.z, acc[2][r]); acc[2][r] = fmaf(w2.w, a4.w, acc[2][r]);
      acc[3][r] = fmaf(w3.x, a4.x, acc[3][r]); acc[3][r] = fmaf(w3.y, a4.y, acc[3][r]);
      acc[3][r] = fmaf(w3.z, a4.z, acc[3][r]); acc[3][r] = fmaf(w3.w, a4.w, acc[3][r]);
    }
  }
  float bb[4];
  #pragma unroll
  for (int i=0;i<4;i++) bb[i] = bias1[c0+i*256] + bias2[c0+i*256];
  #pragma unroll
  for (int r=0;r<8;r++) {
    float4 o;
    o.x = acc[0][r]+bb[0]; o.y = acc[1][r]+bb[1];
    o.z = acc[2][r]+bb[2]; o.w = acc[3][r]+bb[3];
    *(float4*)&g_xp[(size_t)(r0+r)*G4 + c0*4] = o;
  }
}

// ============================================================
// Fused two-layer LSTM scan: 8 clusters x 16 CTAs (one per batch).
// ranks 0-7: layer 0 (xp0 from gmem); ranks 8-15: layer 1 (xp1
// computed in-CTA from smem-resident W_ih1 slice).
// h1 flows layer0 -> everyone via st.async; credits give backpressure.
// ============================================================
__global__ void __launch_bounds__(256,1) __cluster_dims__(16,1,1)
lstm_fused(const float* __restrict__ w_hh0, const float* __restrict__ w_hh1,
           const float* __restrict__ w_ih1, const float* __restrict__ bih1,
           const float* __restrict__ bhh1, const float* __restrict__ thought)
{
  __shared__ __align__(16) float h_s[2][HID];    // own-layer h ring
  __shared__ __align__(16) float h1in[2][HID];   // layer1: incoming h1
  __shared__ __align__(8) unsigned long long mbA[2];  // ring barriers
  __shared__ __align__(8) unsigned long long mbB[2];  // h1-in barriers (layer1)
  __shared__ __align__(8) unsigned long long crd[2];  // credit barriers (layer0)
  extern __shared__ float wih_s[];               // [256][129] (layer1 only)

  const int tid = threadIdx.x;
  const int b   = blockIdx.x >> 4;
  const int rk  = blockIdx.x & 15;
  const int L   = rk >> 3;
  const int j   = rk & 7;
  const int u   = tid >> 3;
  const int kp  = tid & 7;
  const int ug  = 32*j + u;

  const float* w_hh = L ? w_hh1 : w_hh0;
  float wreg[4][32];
  #pragma unroll
  for (int g=0; g<4; g++){
    const float* wp = w_hh + (size_t)(g*256 + ug)*HID + 32*kp;
    #pragma unroll
    for (int q=0;q<8;q++){
      float4 v = *(const float4*)(wp + 4*q);
      wreg[g][4*q+0]=v.x; wreg[g][4*q+1]=v.y; wreg[g][4*q+2]=v.z; wreg[g][4*q+3]=v.w;
    }
  }

  float4 bb4 = make_float4(0.f,0.f,0.f,0.f);
  if (L) {
    #pragma unroll
    for (int g=0; g<4; g++){
      const float* wp = w_ih1 + (size_t)(g*256 + ug)*HID + 32*kp;
      #pragma unroll
      for (int q=0;q<8;q++){
        float4 v = *(const float4*)(wp + 4*q);
        wih_s[tid*WIH_STRIDE + g*32 + 4*q+0] = v.x;
        wih_s[tid*WIH_STRIDE + g*32 + 4*q+1] = v.y;
        wih_s[tid*WIH_STRIDE + g*32 + 4*q+2] = v.z;
        wih_s[tid*WIH_STRIDE + g*32 + 4*q+3] = v.w;
      }
    }
    if (kp == 0) {
      bb4.x = bih1[0*256+ug] + bhh1[0*256+ug];
      bb4.y = bih1[1*256+ug] + bhh1[1*256+ug];
      bb4.z = bih1[2*256+ug] + bhh1[2*256+ug];
      bb4.w = bih1[3*256+ug] + bhh1[3*256+ug];
    }
  }

  const uint32_t A0 = smem_u32(&mbA[0]), A1 = smem_u32(&mbA[1]);
  const uint32_t B0 = smem_u32(&mbB[0]), B1 = smem_u32(&mbB[1]);
  const uint32_t C0 = smem_u32(&crd[0]), C1 = smem_u32(&crd[1]);
  if (tid == 0) {
    mbar_init_(A0, 1); mbar_init_(A1, 1);
    mbar_expect_tx_(A0, 1024); mbar_expect_tx_(A1, 1024);
    if (L) { mbar_init_(B0, 1); mbar_init_(B1, 1);
             mbar_expect_tx_(B0, 1024); mbar_expect_tx_(B1, 1024); }
    else   { mbar_init_(C0, 8); mbar_init_(C1, 8); }
  }
  h_s[0][tid] = thought[b*HID + tid];
  __syncthreads();
  cluster_sync_();   // all barriers initialized before any st.async/arrive

  const uint32_t hs0  = smem_u32(&h_s[0][0]),  hs1  = smem_u32(&h_s[1][0]);
  const uint32_t hin0 = smem_u32(&h1in[0][0]), hin1 = smem_u32(&h1in[1][0]);
  const bool owner = (kp == 0);
  float c = 0.f;

  for (int t = 0; t < STEPS; t++) {
    const int cur = t & 1;

    // layer0: prefetch xp0 before waits
    float4 xpv = bb4;
    if (!L && owner)
      xpv = *(const float4*)&g_xp[(size_t)(t*BATCH + b)*G4 + ug*4];

    // own-layer ring wait: h_{t-1} present in h_s[cur]
    if (t > 0) {
      mbar_wait_(cur ? A1 : A0, ((uint32_t)(t-1) >> 1) & 1u);
      if (tid == 0) mbar_expect_tx_(cur ? A1 : A0, 1024);
    }

    float a0=0.f,a1=0.f,a2=0.f,a3=0.f;
    {
      const float4* h4 = (const float4*)&h_s[cur][32*kp];
      #pragma unroll
      for (int q=0;q<8;q++) {
        float4 hv = h4[q];
        a0=fmaf(wreg[0][4*q+0],hv.x,a0); a0=fmaf(wreg[0][4*q+1],hv.y,a0);
        a0=fmaf(wreg[0][4*q+2],hv.z,a0); a0=fmaf(wreg[0][4*q+3],hv.w,a0);
        a1=fmaf(wreg[1][4*q+0],hv.x,a1); a1=fmaf(wreg[1][4*q+1],hv.y,a1);
        a1=fmaf(wreg[1][4*q+2],hv.z,a1); a1=fmaf(wreg[1][4*q+3],hv.w,a1);
        a2=fmaf(wreg[2][4*q+0],hv.x,a2); a2=fmaf(wreg[2][4*q+1],hv.y,a2);
        a2=fmaf(wreg[2][4*q+2],hv.z,a2); a2=fmaf(wreg[2][4*q+3],hv.w,a2);
        a3=fmaf(wreg[3][4*q+0],hv.x,a3); a3=fmaf(wreg[3][4*q+1],hv.y,a3);
        a3=fmaf(wreg[3][4*q+2],hv.z,a3); a3=fmaf(wreg[3][4*q+3],hv.w,a3);
      }
    }

    if (L) {
      // wait for h1_t, then add xp1 partials from smem W_ih1 slice
      mbar_wait_(cur ? B1 : B0, ((uint32_t)t >> 1) & 1u);
      if (tid == 0) mbar_expect_tx_(cur ? B1 : B0, 1024);
      const float* wp = &wih_s[tid*WIH_STRIDE];
      const float4* h4 = (const float4*)&h1in[cur][32*kp];
      #pragma unroll
      for (int q=0;q<8;q++) {
        float4 hv = h4[q];
        a0=fmaf(wp[0*32+4*q+0],hv.x,a0); a0=fmaf(wp[0*32+4*q+1],hv.y,a0);
        a0=fmaf(wp[0*32+4*q+2],hv.z,a0); a0=fmaf(wp[0*32+4*q+3],hv.w,a0);
        a1=fmaf(wp[1*32+4*q+0],hv.x,a1); a1=fmaf(wp[1*32+4*q+1],hv.y,a1);
        a1=fmaf(wp[1*32+4*q+2],hv.z,a1); a1=fmaf(wp[1*32+4*q+3],hv.w,a1);
        a2=fmaf(wp[2*32+4*q+0],hv.x,a2); a2=fmaf(wp[2*32+4*q+1],hv.y,a2);
        a2=fmaf(wp[2*32+4*q+2],hv.z,a2); a2=fmaf(wp[2*32+4*q+3],hv.w,a2);
        a3=fmaf(wp[3*32+4*q+0],hv.x,a3); a3=fmaf(wp[3*32+4*q+1],hv.y,a3);
        a3=fmaf(wp[3*32+4*q+2],hv.z,a3); a3=fmaf(wp[3*32+4*q+3],hv.w,a3);
      }
    }

    #pragma unroll
    for (int off=4; off>=1; off>>=1) {
      a0 += __shfl_xor_sync(0xffffffffu, a0, off);
      a1 += __shfl_xor_sync(0xffffffffu, a1, off);
      a2 += __shfl_xor_sync(0xffffffffu, a2, off);
      a3 += __shfl_xor_sync(0xffffffffu, a3, off);
    }

    if (L) {
      __syncthreads();   // all h1in[cur] reads complete
      if (tid < 8) mbar_arrive_remote_(cur ? C1 : C0, (uint32_t)tid);  // free slot
    }

    if (owner) {
      float gi = sigmoidf_(a0 + xpv.x);
      float gf = sigmoidf_(a1 + xpv.y);
      float gg = 2.f*sigmoidf_(2.f*(a2 + xpv.z)) - 1.f;   // tanh
      float go = sigmoidf_(a3 + xpv.w);
      c = gf*c + gi*gg;
      float h = go * (2.f*sigmoidf_(2.f*c) - 1.f);
      uint32_t hv = __float_as_uint(h);

      if (L) {
        g_h2[(size_t)(t*BATCH+b)*HID + ug] = h;
        if (t + 1 < STEPS) {
          uint32_t daddr = (cur ? hs0 : hs1) + (uint32_t)ug*4u;  // next-step ring buf
          uint32_t dmb   = cur ? A0 : A1;
          #pragma unroll
          for (int p=8;p<16;p++) st_async_b32_(daddr, dmb, (uint32_t)p, hv);
        }
      } else {
        // credit: layer1 must have freed h1in slot (t-2) before we refill it
        if (t >= 2) mbar_wait_(cur ? C1 : C0, ((uint32_t)(t-2) >> 1) & 1u);
        {
          uint32_t daddr = (cur ? hin1 : hin0) + (uint32_t)ug*4u;  // slot t&1
          uint32_t dmb   = cur ? B1 : B0;
          #pragma unroll
          for (int p=8;p<16;p++) st_async_b32_(daddr, dmb, (uint32_t)p, hv);
        }
        if (t + 1 < STEPS) {
          uint32_t daddr = (cur ? hs0 : hs1) + (uint32_t)ug*4u;
          uint32_t dmb   = cur ? A0 : A1;
          #pragma unroll
          for (int p=0;p<8;p++) st_async_b32_(daddr, dmb, (uint32_t)p, hv);
        }
      }
    }
  }
  cluster_sync_();   // no CTA exits while peers' async traffic may be in flight
}

// ============================================================
// gate MLP fused with gated-h2 split-bf16 conversion (proven)
// ============================================================
__global__ void __launch_bounds__(256) gateacat_kernel(
    const float* __restrict__ gw1, const float* __restrict__ gb1,
    const float* __restrict__ gw2, const float* __restrict__ gb2)
{
  __shared__ __align__(16) float Hs[8][256];
  __shared__ float wp_s[8][8];
  __shared__ float gatev[8];
  const int tid = threadIdx.x;
  const int r0  = blockIdx.x * 8;

  if (r0 >= NROWS) {
    __nv_bfloat16 z = __float2bfloat16(0.f);
    #pragma unroll
    for (int row=0; row<8; row++){
      __nv_bfloat16* rp = g_acat + (size_t)(r0+row)*KCAT;
      rp[tid] = z; rp[HID+tid] = z; rp[2*HID+tid] = z;
    }
    return;
  }

  for (int idx = tid; idx < 8*256; idx += 256) {
    int row = idx >> 8, k = idx & 255;
    Hs[row][k] = g_h2[(size_t)(r0+row)*HID + k];
  }
  __syncthreads();

  float u[8];
  #pragma unroll
  for (int r=0;r<8;r++) u[r]=0.f;
  const float* wrow = gw1 + (size_t)tid*256;
  #pragma unroll 8
  for (int k0=0;k0<256;k0+=4){
    float4 w4 = *(const float4*)(wrow + k0);
    #pragma unroll
    for (int r=0;r<8;r++) {
      float4 a4 = *(const float4*)&Hs[r][k0];
      u[r] = fmaf(w4.x, a4.x, u[r]); u[r] = fmaf(w4.y, a4.y, u[r]);
      u[r] = fmaf(w4.z, a4.z, u[r]); u[r] = fmaf(w4.w, a4.w, u[r]);
    }
  }
  float g2 = gw2[tid], b1v = gb1[tid];
  float p[8];
  #pragma unroll
  for (int r=0;r<8;r++) p[r] = tanhf(u[r] + b1v) * g2;
  #pragma unroll
  for (int off=16; off>=1; off>>=1)
    #pragma unroll
    for (int r=0;r<8;r++) p[r] += __shfl_xor_sync(0xffffffffu, p[r], off);
  if ((tid & 31) == 0)
    #pragma unroll
    for (int r=0;r<8;r++) wp_s[tid>>5][r] = p[r];
  __syncthreads();
  if (tid < 8) {
    float s = 0.f;
    #pragma unroll
    for (int w=0;w<8;w++) s += wp_s[w][tid];
    gatev[tid] = sigmoidf_(s + gb2[0]);
  }
  __syncthreads();

  #pragma unroll
  for (int row=0; row<8; row++){
    float a = Hs[row][tid] * gatev[row];
    __nv_bfloat16 hi = __float2bfloat16(a);
    __nv_bfloat16 lo = __float2bfloat16(a - __bfloat162float(hi));
    __nv_bfloat16* rp = g_acat + (size_t)(r0+row)*KCAT;
    rp[tid] = hi; rp[HID+tid] = lo; rp[2*HID+tid] = hi;
  }
}

// ============================================================
// out_w split conversion
// ============================================================
__global__ void __launch_bounds__(256) wcat_kernel(const float* __restrict__ ow){
  const int v = blockIdx.x, k = threadIdx.x;
  float w = ow[(size_t)v*HID + k];
  __nv_bfloat16 hi = __float2bfloat16(w);
  __nv_bfloat16 lo = __float2bfloat16(w - __bfloat162float(hi));
  __nv_bfloat16* row = g_wcat + (size_t)v*KCAT;
  row[k] = hi; row[HID + k] = hi; row[2*HID + k] = lo;
}

// ============================================================
// vocab GEMM (R10 exact, 2-stage)
// ============================================================
#define KC 64
#define NCHUNK (KCAT/KC)             // 12
#define STAGE_HALF 16384
#define STAGE_SZ   32768
#define EPS_STRIDE 132
#define GSMEM (2*STAGE_SZ + 4096)

__global__ void __launch_bounds__(256) out_gemm_mma(
    const float* __restrict__ ob, float* __restrict__ outp)
{
  extern __shared__ __align__(128) char smg[];
  const uint32_t sbase = smem_u32(smg);
  float* eps = (float*)smg;
  const int tid  = threadIdx.x;
  const int wid  = tid >> 5;
  const int lane = tid & 31;
  const int bn = blockIdx.x * 128;
  const int bm = blockIdx.y * 128;
  const int wm = (wid & 1) * 64;
  const int wn = (wid >> 1) * 32;

  const int lrow = tid >> 1;
  const int lseg4 = (tid & 1) * 4;
  #pragma unroll
  for (int c = 0; c < 2; c++) {
    const uint32_t st = sbase + c*STAGE_SZ;
    const char* wg = (const char*)g_wcat + ((size_t)(bm+lrow)*KCAT + c*KC)*2;
    const char* ag = (const char*)g_acat + ((size_t)(bn+lrow)*KCAT + c*KC)*2;
    #pragma unroll
    for (int q=0;q<4;q++){
      uint32_t off = sw128_((uint32_t)(lrow*128 + (lseg4+q)*16));
      cp_async16_(st + off, wg + (lseg4+q)*16);
      cp_async16_(st + STAGE_HALF + off, ag + (lseg4+q)*16);
    }
    CP_COMMIT();
  }
  float acc[4][4][4];
  #pragma unroll
  for (int i=0;i<4;i++)
    #pragma unroll
    for (int jj=0;jj<4;jj++)
      #pragma unroll
      for (int v=0;v<4;v++) acc[i][jj][v]=0.f;
  const uint32_t a_row = (uint32_t)(lane & 15);
  const uint32_t a_k16 = (uint32_t)((lane >> 4) * 16);
  const uint32_t b_row = (uint32_t)((lane & 7) + ((lane & 16) >> 1));
  const uint32_t b_k16 = (uint32_t)((lane & 8) ? 16 : 0);
  for (int c = 0; c < NCHUNK; c++) {
    CP_WAIT1();
    __syncthreads();
    const uint32_t wbase = sbase + (c & 1)*STAGE_SZ;
    const uint32_t abase = wbase + STAGE_HALF;
    #pragma unroll
    for (int k = 0; k < 4; k++) {
      uint32_t af[4][4], bf[2][4];
      #pragma unroll
      for (int mt=0; mt<4; mt++)
        ldsm_x4_(af[mt], wbase + sw128_((uint32_t)((wm + mt*16 + a_row)*128) + k*32 + a_k16));
      #pragma unroll
      for (int nt2=0; nt2<2; nt2++)
        ldsm_x4_(bf[nt2], abase + sw128_((uint32_t)((wn + nt2*16 + b_row)*128) + k*32 + b_k16));
      #pragma unroll
      for (int mt=0; mt<4; mt++)
        #pragma unroll
        for (int nt=0; nt<4; nt++)
          mma16816_(acc[mt][nt], af[mt], &bf[nt>>1][(nt&1)*2]);
    }
    __syncthreads();
    if (c + 2 < NCHUNK) {
      const uint32_t st = sbase + (c & 1)*STAGE_SZ;
      const char* wg = (const char*)g_wcat + ((size_t)(bm+lrow)*KCAT + (c+2)*KC)*2;
      const char* ag = (const char*)g_acat + ((size_t)(bn+lrow)*KCAT + (c+2)*KC)*2;
      #pragma unroll
      for (int q=0;q<4;q++){
        uint32_t off = sw128_((uint32_t)(lrow*128 + (lseg4+q)*16));
        cp_async16_(st + off, wg + (lseg4+q)*16);
        cp_async16_(st + STAGE_HALF + off, ag + (lseg4+q)*16);
      }
    }
    CP_COMMIT();
  }
  CP_WAIT0();
  {
    const int mq = lane >> 2;
    const int nq = (lane & 3) * 2;
    #pragma unroll
    for (int mt=0; mt<4; mt++)
      #pragma unroll
      for (int nt=0; nt<4; nt++){
        int m0 = wm + mt*16 + mq;
        int n0 = wn + nt*8 + nq;
        eps[(n0  )*EPS_STRIDE + m0    ] = acc[mt][nt][0];
        eps[(n0+1)*EPS_STRIDE + m0    ] = acc[mt][nt][1];
        eps[(n0  )*EPS_STRIDE + m0 + 8] = acc[mt][nt][2];
        eps[(n0+1)*EPS_STRIDE + m0 + 8] = acc[mt][nt][3];
      }
  }
  __syncthreads();
  {
    const int mo = (tid & 15) * 8;
    const int vg = bm + mo;
    float4 ob0 = *(const float4*)&ob[vg];
    float4 ob1 = *(const float4*)&ob[vg+4];
    #pragma unroll
    for (int it = 0; it < 8; it++) {
      int n = (tid >> 4) + it*16;
      int r = bn + n;
      if (r < NROWS) {
        const float* ep = eps + n*EPS_STRIDE + mo;
        float4 v0 = *(const float4*)ep;
        float4 v1 = *(const float4*)(ep+4);
        v0.x+=ob0.x; v0.y+=ob0.y; v0.z+=ob0.z; v0.w+=ob0.w;
        v1.x+=ob1.x; v1.y+=ob1.y; v1.z+=ob1.z; v1.w+=ob1.w;
        float* op = outp + (size_t)((r & 7)*STEPS + (r >> 3))*VOCAB + vg;
        *(float4*)op     = v0;
        *(float4*)(op+4) = v1;
      }
    }
  }
}

// ============================================================
extern "C" void kernel_launch(void* const* d_in, const int* in_sizes, int n_in,
                              void* d_out, int out_size) {
  const float* thought = (const float*)d_in[0];
  const int*   captions= (const int*)  d_in[1];
  const float* emb_w   = (const float*)d_in[2];
  const float* w_ih0   = (const float*)d_in[3];
  const float* w_hh0   = (const float*)d_in[4];
  const float* b_ih0   = (const float*)d_in[5];
  const float* b_hh0   = (const float*)d_in[6];
  const float* w_ih1   = (const float*)d_in[7];
  const float* w_hh1   = (const float*)d_in[8];
  const float* b_ih1   = (const float*)d_in[9];
  const float* b_hh1   = (const float*)d_in[10];
  const float* gw1     = (const float*)d_in[11];
  const float* gb1     = (const float*)d_in[12];
  const float* gw2     = (const float*)d_in[13];
  const float* gb2     = (const float*)d_in[14];
  const float* ow      = (const float*)d_in[15];
  const float* ob      = (const float*)d_in[16];
  float* outp = (float*)d_out;

  static cudaStream_t s1 = nullptr;
  static cudaEvent_t ev0 = nullptr, evW = nullptr;
  if (!s1) {
    cudaStreamCreate(&s1);
    cudaEventCreateWithFlags(&ev0, cudaEventDisableTiming);
    cudaEventCreateWithFlags(&evW, cudaEventDisableTiming);
    cudaFuncSetAttribute(out_gemm_mma, cudaFuncAttributeMaxDynamicSharedMemorySize, GSMEM);
    cudaFuncSetAttribute(lstm_fused, cudaFuncAttributeMaxDynamicSharedMemorySize, WIH_BYTES);
    cudaFuncSetAttribute(lstm_fused, cudaFuncAttributeNonPortableClusterSizeAllowed, 1);
  }

  // wcat overlaps xp0 (both retire before the fused scan needs clean placement)
  cudaEventRecord(ev0, 0);
  cudaStreamWaitEvent(s1, ev0, 0);
  wcat_kernel<<<VOCAB, 256, 0, s1>>>(ow);
  cudaEventRecord(evW, s1);

  xp0_kernel<<<STEPS, 256>>>(captions, emb_w, w_ih0, b_ih0, b_hh0);
  lstm_fused<<<128, 256, WIH_BYTES>>>(w_hh0, w_hh1, w_ih1, b_ih1, b_hh1, thought);
  gateacat_kernel<<<512, 256>>>(gw1, gb1, gw2, gb2);
  cudaStreamWaitEvent(0, evW, 0);
  dim3 gg(NPAD/128, VOCAB/128);   // (32, 250)
  out_gemm_mma<<<gg, 256, GSMEM>>>(ob, outp);
}

// round 13
// speedup vs baseline: 1.6337x; 1.6337x over previous
#include <cuda_runtime.h>
#include <cuda_bf16.h>
#include <cstdint>
#include <math.h>

#define STEPS 511
#define BATCH 8
#define HID   256
#define G4    1024
#define VOCAB 32000
#define NROWS (STEPS*BATCH)   // 4088
#define NPAD  4096
#define KCAT  768             // [hi | hi/lo split] concat K

// ---------------- scratch (no allocs allowed) ----------------
__device__ float g_xp[STEPS*BATCH*G4];                // gate-interleaved: [r][unit*4+gate]
__device__ float g_h1[STEPS*BATCH*HID];
__device__ float g_h2[STEPS*BATCH*HID];
__device__ __nv_bfloat16 g_wcat[(size_t)VOCAB*KCAT];  // 49 MB  out_w split
__device__ __nv_bfloat16 g_acat[(size_t)NPAD*KCAT];   // 6.3 MB (h1-split, then gated-h2-split)
__device__ __nv_bfloat16 g_xw[(size_t)G4*KCAT];       // 1.5 MB  w_ih1 split

__device__ __forceinline__ float sigmoidf_(float x){ return 1.0f/(1.0f + __expf(-x)); }

__device__ __forceinline__ uint32_t smem_u32(const void* p){
  return (uint32_t)__cvta_generic_to_shared(p);
}
__device__ __forceinline__ void mbar_init_(uint32_t a, uint32_t cnt){
  asm volatile("mbarrier.init.shared.b64 [%0], %1;" :: "r"(a), "r"(cnt) : "memory");
}
__device__ __forceinline__ void mbar_expect_tx_(uint32_t a, uint32_t bytes){
  asm volatile("mbarrier.arrive.expect_tx.shared.b64 _, [%0], %1;" :: "r"(a), "r"(bytes) : "memory");
}
__device__ __forceinline__ void mbar_wait_(uint32_t a, uint32_t phase){
  asm volatile("{\n\t.reg .pred P;\n\t"
    "WL_%=:\n\t"
    "mbarrier.try_wait.parity.acquire.cta.shared::cta.b64 P, [%0], %1, 0x989680;\n\t"
    "@P bra.uni WD_%=;\n\t"
    "bra.uni WL_%=;\n\t"
    "WD_%=:\n\t}" :: "r"(a), "r"(phase) : "memory");
}
__device__ __forceinline__ void st_async_b32_(uint32_t saddr, uint32_t smbar, uint32_t rank, uint32_t v){
  asm volatile("{\n\t.reg .b32 ra, rb;\n\t"
    "mapa.shared::cluster.u32 ra, %0, %2;\n\t"
    "mapa.shared::cluster.u32 rb, %1, %2;\n\t"
    "st.async.shared::cluster.mbarrier::complete_tx::bytes.b32 [ra], %3, [rb];\n\t}"
    :: "r"(saddr), "r"(smbar), "r"(rank), "r"(v) : "memory");
}
__device__ __forceinline__ void cluster_sync_(){
  asm volatile("barrier.cluster.arrive.aligned;" ::: "memory");
  asm volatile("barrier.cluster.wait.aligned;"   ::: "memory");
}
__device__ __forceinline__ void cp_async16_(uint32_t saddr, const void* gaddr){
  asm volatile("cp.async.cg.shared.global [%0], [%1], 16;" :: "r"(saddr), "l"(gaddr) : "memory");
}
#define CP_COMMIT() asm volatile("cp.async.commit_group;" ::: "memory")
#define CP_WAIT1()  asm volatile("cp.async.wait_group 1;" ::: "memory")
#define CP_WAIT0()  asm volatile("cp.async.wait_group 0;" ::: "memory")

__device__ __forceinline__ void ldsm_x4_(uint32_t* r, uint32_t addr){
  asm volatile("ldmatrix.sync.aligned.m8n8.x4.shared.b16 {%0,%1,%2,%3}, [%4];"
    : "=r"(r[0]), "=r"(r[1]), "=r"(r[2]), "=r"(r[3]) : "r"(addr));
}
__device__ __forceinline__ void mma16816_(float* d, const uint32_t* a, const uint32_t* b){
  asm volatile("mma.sync.aligned.m16n8k16.row.col.f32.bf16.bf16.f32 "
    "{%0,%1,%2,%3}, {%4,%5,%6,%7}, {%8,%9}, {%0,%1,%2,%3};"
    : "+f"(d[0]), "+f"(d[1]), "+f"(d[2]), "+f"(d[3])
    : "r"(a[0]), "r"(a[1]), "r"(a[2]), "r"(a[3]), "r"(b[0]), "r"(b[1]));
}
static __device__ __forceinline__ uint32_t sw128_(uint32_t b){ return b ^ ((b >> 3) & 0x70u); }

// ============================================================
// Layer-0 input projection (K=128): 16 rows per CTA (grid 256)
// halves W L2 re-reads vs the 8-row version
// ============================================================
__global__ void __launch_bounds__(256) xp0_kernel(
    const int* __restrict__ captions, const float* __restrict__ emb_w,
    const float* __restrict__ W, const float* __restrict__ bias1,
    const float* __restrict__ bias2)
{
  __shared__ __align__(16) float As[16][128];
  const int tid = threadIdx.x;
  const int r0  = blockIdx.x * 16;

  for (int idx = tid; idx < 16*128; idx += 256) {
    int row = idx >> 7, k = idx & 127;
    int r = r0 + row;
    float v = 0.f;
    if (r < NROWS) {
      int b = r & 7, t = r >> 3;
      v = emb_w[(size_t)captions[b*512 + t] * 128 + k];
    }
    As[row][k] = v;
  }
  __syncthreads();

  float acc[4][16];
  #pragma unroll
  for (int i=0;i<4;i++)
    #pragma unroll
    for (int r=0;r<16;r++) acc[i][r]=0.f;

  const int c0 = tid;   // unit
  for (int k0 = 0; k0 < 128; k0 += 4) {
    float4 w0 = *(const float4*)&W[(size_t)(c0      )*128 + k0];
    float4 w1 = *(const float4*)&W[(size_t)(c0+256)*128 + k0];
    float4 w2 = *(const float4*)&W[(size_t)(c0+512)*128 + k0];
    float4 w3 = *(const float4*)&W[(size_t)(c0+768)*128 + k0];
    #pragma unroll
    for (int r=0;r<16;r++) {
      float4 a4 = *(const float4*)&As[r][k0];
      acc[0][r] = fmaf(w0.x, a4.x, acc[0][r]); acc[0][r] = fmaf(w0.y, a4.y, acc[0][r]);
      acc[0][r] = fmaf(w0.z, a4.z, acc[0][r]); acc[0][r] = fmaf(w0.w, a4.w, acc[0][r]);
      acc[1][r] = fmaf(w1.x, a4.x, acc[1][r]); acc[1][r] = fmaf(w1.y, a4.y, acc[1][r]);
      acc[1][r] = fmaf(w1.z, a4.z, acc[1][r]); acc[1][r] = fmaf(w1.w, a4.w, acc[1][r]);
      acc[2][r] = fmaf(w2.x, a4.x, acc[2][r]); acc[2][r] = fmaf(w2.y, a4.y, acc[2][r]);
      acc[2][r] = fmaf(w2.z, a4.z, acc[2][r]); acc[2][r] = fmaf(w2.w, a4.w, acc[2][r]);
      acc[3][r] = fmaf(w3.x, a4.x, acc[3][r]); acc[3][r] = fmaf(w3.y, a4.y, acc[3][r]);
      acc[3][r] = fmaf(w3.z, a4.z, acc[3][r]); acc[3][r] = fmaf(w3.w, a4.w, acc[3][r]);
    }
  }
  float bb[4];
  #pragma unroll
  for (int i=0;i<4;i++) bb[i] = bias1[c0+i*256] + bias2[c0+i*256];
  #pragma unroll
  for (int r=0;r<16;r++) {
    if (r0 + r < NROWS) {
      float4 o;
      o.x = acc[0][r]+bb[0]; o.y = acc[1][r]+bb[1];
      o.z = acc[2][r]+bb[2]; o.w = acc[3][r]+bb[3];
      *(float4*)&g_xp[(size_t)(r0+r)*G4 + c0*4] = o;
    }
  }
}

// ============================================================
// LSTM scan (R10 exact)
// ============================================================
__global__ __launch_bounds__(256,1) __cluster_dims__(8,1,1)
void lstm_scan2(const float* __restrict__ w_hh,
                const float* __restrict__ thought,
                int layer)
{
  __shared__ __align__(16) float h_s[2][HID];
  __shared__ __align__(8) unsigned long long mbar_sto[2];

  float* __restrict__ h_out = layer ? g_h2 : g_h1;

  const int tid = threadIdx.x;
  const int b   = blockIdx.x >> 3;
  const int j   = blockIdx.x & 7;
  const int u   = tid >> 3;
  const int kp  = tid & 7;
  const int ug  = 32*j + u;

  float wreg[4][32];
  #pragma unroll
  for (int g=0; g<4; g++){
    const float* wp = w_hh + (size_t)(g*256 + ug)*HID + 32*kp;
    #pragma unroll
    for (int q=0;q<8;q++){
      float4 v = *(const float4*)(wp + 4*q);
      wreg[g][4*q+0]=v.x; wreg[g][4*q+1]=v.y; wreg[g][4*q+2]=v.z; wreg[g][4*q+3]=v.w;
    }
  }

  const uint32_t mb0 = smem_u32(&mbar_sto[0]);
  const uint32_t mb1 = smem_u32(&mbar_sto[1]);
  if (tid == 0) {
    mbar_init_(mb0, 1); mbar_init_(mb1, 1);
    mbar_expect_tx_(mb0, 1024); mbar_expect_tx_(mb1, 1024);
  }
  h_s[0][tid] = thought[b*HID + tid];
  __syncthreads();
  cluster_sync_();

  const uint32_t hs0 = smem_u32(&h_s[0][0]);
  const uint32_t hs1 = smem_u32(&h_s[1][0]);
  const bool owner = (kp == 0);
  float c = 0.f;

  for (int t = 0; t < STEPS; t++) {
    const int cur = t & 1;

    float4 xpv = make_float4(0.f,0.f,0.f,0.f);
    if (owner)
      xpv = *(const float4*)&g_xp[(size_t)(t*BATCH + b)*G4 + ug*4];

    if (t > 0) {
      mbar_wait_(cur ? mb1 : mb0, ((uint32_t)(t-1) >> 1) & 1u);
      if (tid == 0) mbar_expect_tx_(cur ? mb1 : mb0, 1024);
    }

    float a0=0.f,a1=0.f,a2=0.f,a3=0.f;
    const float4* h4 = (const float4*)&h_s[cur][32*kp];
    #pragma unroll
    for (int q=0;q<8;q++) {
      float4 hv = h4[q];
      a0=fmaf(wreg[0][4*q+0],hv.x,a0); a0=fmaf(wreg[0][4*q+1],hv.y,a0);
      a0=fmaf(wreg[0][4*q+2],hv.z,a0); a0=fmaf(wreg[0][4*q+3],hv.w,a0);
      a1=fmaf(wreg[1][4*q+0],hv.x,a1); a1=fmaf(wreg[1][4*q+1],hv.y,a1);
      a1=fmaf(wreg[1][4*q+2],hv.z,a1); a1=fmaf(wreg[1][4*q+3],hv.w,a1);
      a2=fmaf(wreg[2][4*q+0],hv.x,a2); a2=fmaf(wreg[2][4*q+1],hv.y,a2);
      a2=fmaf(wreg[2][4*q+2],hv.z,a2); a2=fmaf(wreg[2][4*q+3],hv.w,a2);
      a3=fmaf(wreg[3][4*q+0],hv.x,a3); a3=fmaf(wreg[3][4*q+1],hv.y,a3);
      a3=fmaf(wreg[3][4*q+2],hv.z,a3); a3=fmaf(wreg[3][4*q+3],hv.w,a3);
    }
    #pragma unroll
    for (int off=4; off>=1; off>>=1) {
      a0 += __shfl_xor_sync(0xffffffffu, a0, off);
      a1 += __shfl_xor_sync(0xffffffffu, a1, off);
      a2 += __shfl_xor_sync(0xffffffffu, a2, off);
      a3 += __shfl_xor_sync(0xffffffffu, a3, off);
    }

    if (owner) {
      float gi = sigmoidf_(a0 + xpv.x);
      float gf = sigmoidf_(a1 + xpv.y);
      float gg = 2.f*sigmoidf_(2.f*(a2 + xpv.z)) - 1.f;   // tanh
      float go = sigmoidf_(a3 + xpv.w);
      c = gf*c + gi*gg;
      float h = go * (2.f*sigmoidf_(2.f*c) - 1.f);
      h_out[(size_t)(t*BATCH+b)*HID + ug] = h;
      if (t + 1 < STEPS) {
        uint32_t daddr = (cur ? hs0 : hs1) + (uint32_t)ug*4u;
        uint32_t dmb   = cur ? mb0 : mb1;
        uint32_t hv = __float_as_uint(h);
        #pragma unroll
        for (int p=0;p<8;p++) st_async_b32_(daddr, dmb, (uint32_t)p, hv);
      }
    }
  }
}

// ============================================================
// gate MLP fused with gated-h2 split-bf16 conversion (R10 exact)
// ============================================================
__global__ void __launch_bounds__(256) gateacat_kernel(
    const float* __restrict__ gw1, const float* __restrict__ gb1,
    const float* __restrict__ gw2, const float* __restrict__ gb2)
{
  __shared__ __align__(16) float Hs[8][256];
  __shared__ float wp_s[8][8];
  __shared__ float gatev[8];
  const int tid = threadIdx.x;
  const int r0  = blockIdx.x * 8;

  if (r0 >= NROWS) {
    __nv_bfloat16 z = __float2bfloat16(0.f);
    #pragma unroll
    for (int row=0; row<8; row++){
      __nv_bfloat16* rp = g_acat + (size_t)(r0+row)*KCAT;
      rp[tid] = z; rp[HID+tid] = z; rp[2*HID+tid] = z;
    }
    return;
  }

  for (int idx = tid; idx < 8*256; idx += 256) {
    int row = idx >> 8, k = idx & 255;
    Hs[row][k] = g_h2[(size_t)(r0+row)*HID + k];
  }
  __syncthreads();

  float u[8];
  #pragma unroll
  for (int r=0;r<8;r++) u[r]=0.f;
  const float* wrow = gw1 + (size_t)tid*256;
  #pragma unroll 8
  for (int k0=0;k0<256;k0+=4){
    float4 w4 = *(const float4*)(wrow + k0);
    #pragma unroll
    for (int r=0;r<8;r++) {
      float4 a4 = *(const float4*)&Hs[r][k0];
      u[r] = fmaf(w4.x, a4.x, u[r]); u[r] = fmaf(w4.y, a4.y, u[r]);
      u[r] = fmaf(w4.z, a4.z, u[r]); u[r] = fmaf(w4.w, a4.w, u[r]);
    }
  }
  float g2 = gw2[tid], b1v = gb1[tid];
  float p[8];
  #pragma unroll
  for (int r=0;r<8;r++) p[r] = tanhf(u[r] + b1v) * g2;
  #pragma unroll
  for (int off=16; off>=1; off>>=1)
    #pragma unroll
    for (int r=0;r<8;r++) p[r] += __shfl_xor_sync(0xffffffffu, p[r], off);
  if ((tid & 31) == 0)
    #pragma unroll
    for (int r=0;r<8;r++) wp_s[tid>>5][r] = p[r];
  __syncthreads();
  if (tid < 8) {
    float s = 0.f;
    #pragma unroll
    for (int w=0;w<8;w++) s += wp_s[w][tid];
    gatev[tid] = sigmoidf_(s + gb2[0]);
  }
  __syncthreads();

  #pragma unroll
  for (int row=0; row<8; row++){
    float a = Hs[row][tid] * gatev[row];
    __nv_bfloat16 hi = __float2bfloat16(a);
    __nv_bfloat16 lo = __float2bfloat16(a - __bfloat162float(hi));
    __nv_bfloat16* rp = g_acat + (size_t)(r0+row)*KCAT;
    rp[tid] = hi; rp[HID+tid] = lo; rp[2*HID+tid] = hi;
  }
}

// ============================================================
// split-bf16 conversion kernels (R10 exact)
// ============================================================
__global__ void __launch_bounds__(256) wcat_kernel(const float* __restrict__ ow){
  const int v = blockIdx.x, k = threadIdx.x;
  float w = ow[(size_t)v*HID + k];
  __nv_bfloat16 hi = __float2bfloat16(w);
  __nv_bfloat16 lo = __float2bfloat16(w - __bfloat162float(hi));
  __nv_bfloat16* row = g_wcat + (size_t)v*KCAT;
  row[k] = hi; row[HID + k] = hi; row[2*HID + k] = lo;
}

__global__ void __launch_bounds__(256) wihcvt_kernel(const float* __restrict__ wih){
  const int m = blockIdx.x, k = threadIdx.x;
  float w = wih[(size_t)m*HID + k];
  __nv_bfloat16 hi = __float2bfloat16(w);
  __nv_bfloat16 lo = __float2bfloat16(w - __bfloat162float(hi));
  __nv_bfloat16* row = g_xw + (size_t)m*KCAT;
  row[k] = hi; row[HID + k] = hi; row[2*HID + k] = lo;
}

__global__ void __launch_bounds__(256) h1cvt_kernel(){
  const int r = blockIdx.x, k = threadIdx.x;
  __nv_bfloat16* row = g_acat + (size_t)r*KCAT;
  if (r < NROWS) {
    float a = g_h1[(size_t)r*HID + k];
    __nv_bfloat16 hi = __float2bfloat16(a);
    __nv_bfloat16 lo = __float2bfloat16(a - __bfloat162float(hi));
    row[k] = hi; row[HID + k] = lo; row[2*HID + k] = hi;
  } else {
    __nv_bfloat16 z = __float2bfloat16(0.f);
    row[k] = z; row[HID + k] = z; row[2*HID + k] = z;
  }
}

// ============================================================
// 2-stage mma mainloop macro (R10 + post-WAIT0 sync race fix)
// ============================================================
#define KC 64
#define NCHUNK (KCAT/KC)             // 12
#define STAGE_HALF 16384
#define STAGE_SZ   32768
#define EPS_STRIDE 132
#define XSMEM (2*STAGE_SZ + 4096)

#define MMA_MAINLOOP(WSRC, ASRC)                                                  \
  const int lrow = tid >> 1;                                                      \
  const int lseg4 = (tid & 1) * 4;                                                \
  _Pragma("unroll")                                                               \
  for (int c = 0; c < 2; c++) {                                                   \
    const uint32_t st = sbase + c*STAGE_SZ;                                       \
    const char* wg = (const char*)(WSRC) + ((size_t)(bm+lrow)*KCAT + c*KC)*2;     \
    const char* ag = (const char*)(ASRC) + ((size_t)(bn+lrow)*KCAT + c*KC)*2;     \
    _Pragma("unroll")                                                             \
    for (int q=0;q<4;q++){                                                        \
      uint32_t off = sw128_((uint32_t)(lrow*128 + (lseg4+q)*16));                 \
      cp_async16_(st + off, wg + (lseg4+q)*16);                                   \
      cp_async16_(st + STAGE_HALF + off, ag + (lseg4+q)*16);                      \
    }                                                                             \
    CP_COMMIT();                                                                  \
  }                                                                               \
  float acc[4][4][4];                                                             \
  _Pragma("unroll")                                                               \
  for (int i=0;i<4;i++)                                                           \
    _Pragma("unroll")                                                             \
    for (int jj=0;jj<4;jj++)                                                      \
      _Pragma("unroll")                                                           \
      for (int v=0;v<4;v++) acc[i][jj][v]=0.f;                                    \
  const uint32_t a_row = (uint32_t)(lane & 15);                                   \
  const uint32_t a_k16 = (uint32_t)((lane >> 4) * 16);                            \
  const uint32_t b_row = (uint32_t)((lane & 7) + ((lane & 16) >> 1));             \
  const uint32_t b_k16 = (uint32_t)((lane & 8) ? 16 : 0);                         \
  for (int c = 0; c < NCHUNK; c++) {                                              \
    CP_WAIT1();                                                                   \
    __syncthreads();                                                              \
    const uint32_t wbase = sbase + (c & 1)*STAGE_SZ;                              \
    const uint32_t abase = wbase + STAGE_HALF;                                    \
    _Pragma("unroll")                                                             \
    for (int k = 0; k < 4; k++) {                                                 \
      uint32_t af[4][4], bf[2][4];                                                \
      _Pragma("unroll")                                                           \
      for (int mt=0; mt<4; mt++)                                                  \
        ldsm_x4_(af[mt], wbase + sw128_((uint32_t)((wm + mt*16 + a_row)*128) + k*32 + a_k16)); \
      _Pragma("unroll")                                                           \
      for (int nt2=0; nt2<2; nt2++)                                               \
        ldsm_x4_(bf[nt2], abase + sw128_((uint32_t)((wn + nt2*16 + b_row)*128) + k*32 + b_k16)); \
      _Pragma("unroll")                                                           \
      for (int mt=0; mt<4; mt++)                                                  \
        _Pragma("unroll")                                                         \
        for (int nt=0; nt<4; nt++)                                                \
          mma16816_(acc[mt][nt], af[mt], &bf[nt>>1][(nt&1)*2]);                   \
    }                                                                             \
    __syncthreads();                                                              \
    if (c + 2 < NCHUNK) {                                                         \
      const uint32_t st = sbase + (c & 1)*STAGE_SZ;                               \
      const char* wg = (const char*)(WSRC) + ((size_t)(bm+lrow)*KCAT + (c+2)*KC)*2; \
      const char* ag = (const char*)(ASRC) + ((size_t)(bn+lrow)*KCAT + (c+2)*KC)*2; \
      _Pragma("unroll")                                                           \
      for (int q=0;q<4;q++){                                                      \
        uint32_t off = sw128_((uint32_t)(lrow*128 + (lseg4+q)*16));               \
        cp_async16_(st + off, wg + (lseg4+q)*16);                                 \
        cp_async16_(st + STAGE_HALF + off, ag + (lseg4+q)*16);                    \
      }                                                                           \
    }                                                                             \
    CP_COMMIT();                                                                  \
  }                                                                               \
  CP_WAIT0();                                                                     \
  __syncthreads();                                                                \
  {                                                                               \
    const int mq = lane >> 2;                                                     \
    const int nq = (lane & 3) * 2;                                                \
    _Pragma("unroll")                                                             \
    for (int mt=0; mt<4; mt++)                                                    \
      _Pragma("unroll")                                                           \
      for (int nt=0; nt<4; nt++){                                                 \
        int m0 = wm + mt*16 + mq;                                                 \
        int n0 = wn + nt*8 + nq;                                                  \
        eps[(n0  )*EPS_STRIDE + m0    ] = acc[mt][nt][0];                         \
        eps[(n0+1)*EPS_STRIDE + m0    ] = acc[mt][nt][1];                         \
        eps[(n0  )*EPS_STRIDE + m0 + 8] = acc[mt][nt][2];                         \
        eps[(n0+1)*EPS_STRIDE + m0 + 8] = acc[mt][nt][3];                         \
      }                                                                           \
  }                                                                               \
  __syncthreads();

// ============================================================
// vocab GEMM: 3-stage cp.async ring, one sync per chunk
// ============================================================
#define GSMEM3 (3*STAGE_SZ)          // 96KB; eps (67.6KB) overlays

__global__ void __launch_bounds__(256) out_gemm_mma(
    const float* __restrict__ ob, float* __restrict__ outp)
{
  extern __shared__ __align__(128) char smg[];
  const uint32_t sbase = smem_u32(smg);
  float* eps = (float*)smg;
  const int tid  = threadIdx.x;
  const int wid  = tid >> 5;
  const int lane = tid & 31;
  const int bn = blockIdx.x * 128;
  const int bm = blockIdx.y * 128;
  const int wm = (wid & 1) * 64;
  const int wn = (wid >> 1) * 32;

  const int lrow = tid >> 1;
  const int lseg4 = (tid & 1) * 4;
  #pragma unroll
  for (int c = 0; c < 2; c++) {
    const uint32_t st = sbase + c*STAGE_SZ;
    const char* wg = (const char*)g_wcat + ((size_t)(bm+lrow)*KCAT + c*KC)*2;
    const char* ag = (const char*)g_acat + ((size_t)(bn+lrow)*KCAT + c*KC)*2;
    #pragma unroll
    for (int q=0;q<4;q++){
      uint32_t off = sw128_((uint32_t)(lrow*128 + (lseg4+q)*16));
      cp_async16_(st + off, wg + (lseg4+q)*16);
      cp_async16_(st + STAGE_HALF + off, ag + (lseg4+q)*16);
    }
    CP_COMMIT();
  }
  float acc[4][4][4];
  #pragma unroll
  for (int i=0;i<4;i++)
    #pragma unroll
    for (int jj=0;jj<4;jj++)
      #pragma unroll
      for (int v=0;v<4;v++) acc[i][jj][v]=0.f;
  const uint32_t a_row = (uint32_t)(lane & 15);
  const uint32_t a_k16 = (uint32_t)((lane >> 4) * 16);
  const uint32_t b_row = (uint32_t)((lane & 7) + ((lane & 16) >> 1));
  const uint32_t b_k16 = (uint32_t)((lane & 8) ? 16 : 0);

  int s = 0, sw = 2;
  for (int c = 0; c < NCHUNK; c++) {
    CP_WAIT1();          // chunk c complete (chunk c+1 may still be in flight)
    __syncthreads();     // chunk-c data visible to all; stage sw (= c-1) free
    if (c + 2 < NCHUNK) {
      const uint32_t st = sbase + sw*STAGE_SZ;
      const char* wg = (const char*)g_wcat + ((size_t)(bm+lrow)*KCAT + (c+2)*KC)*2;
      const char* ag = (const char*)g_acat + ((size_t)(bn+lrow)*KCAT + (c+2)*KC)*2;
      #pragma unroll
      for (int q=0;q<4;q++){
        uint32_t off = sw128_((uint32_t)(lrow*128 + (lseg4+q)*16));
        cp_async16_(st + off, wg + (lseg4+q)*16);
        cp_async16_(st + STAGE_HALF + off, ag + (lseg4+q)*16);
      }
    }
    CP_COMMIT();         // uniform group accounting (empty near the tail)
    const uint32_t wbase = sbase + s*STAGE_SZ;
    const uint32_t abase = wbase + STAGE_HALF;
    #pragma unroll
    for (int k = 0; k < 4; k++) {
      uint32_t af[4][4], bf[2][4];
      #pragma unroll
      for (int mt=0; mt<4; mt++)
        ldsm_x4_(af[mt], wbase + sw128_((uint32_t)((wm + mt*16 + a_row)*128) + k*32 + a_k16));
      #pragma unroll
      for (int nt2=0; nt2<2; nt2++)
        ldsm_x4_(bf[nt2], abase + sw128_((uint32_t)((wn + nt2*16 + b_row)*128) + k*32 + b_k16));
      #pragma unroll
      for (int mt=0; mt<4; mt++)
        #pragma unroll
        for (int nt=0; nt<4; nt++)
          mma16816_(acc[mt][nt], af[mt], &bf[nt>>1][(nt&1)*2]);
    }
    s  = (s  + 1 == 3) ? 0 : s  + 1;
    sw = (sw + 1 == 3) ? 0 : sw + 1;
  }
  CP_WAIT0();
  __syncthreads();       // all mma smem reads done before eps overlay
  {
    const int mq = lane >> 2;
    const int nq = (lane & 3) * 2;
    #pragma unroll
    for (int mt=0; mt<4; mt++)
      #pragma unroll
      for (int nt=0; nt<4; nt++){
        int m0 = wm + mt*16 + mq;
        int n0 = wn + nt*8 + nq;
        eps[(n0  )*EPS_STRIDE + m0    ] = acc[mt][nt][0];
        eps[(n0+1)*EPS_STRIDE + m0    ] = acc[mt][nt][1];
        eps[(n0  )*EPS_STRIDE + m0 + 8] = acc[mt][nt][2];
        eps[(n0+1)*EPS_STRIDE + m0 + 8] = acc[mt][nt][3];
      }
  }
  __syncthreads();
  {
    const int mo = (tid & 15) * 8;
    const int vg = bm + mo;
    float4 ob0 = *(const float4*)&ob[vg];
    float4 ob1 = *(const float4*)&ob[vg+4];
    #pragma unroll
    for (int it = 0; it < 8; it++) {
      int n = (tid >> 4) + it*16;
      int r = bn + n;
      if (r < NROWS) {
        const float* ep = eps + n*EPS_STRIDE + mo;
        float4 v0 = *(const float4*)ep;
        float4 v1 = *(const float4*)(ep+4);
        v0.x+=ob0.x; v0.y+=ob0.y; v0.z+=ob0.z; v0.w+=ob0.w;
        v1.x+=ob1.x; v1.y+=ob1.y; v1.z+=ob1.z; v1.w+=ob1.w;
        float* op = outp + (size_t)((r & 7)*STEPS + (r >> 3))*VOCAB + vg;
        *(float4*)op     = v0;
        *(float4*)(op+4) = v1;
      }
    }
  }
}

// ============================================================
// xp1 GEMM (R10 exact, uses 2-stage macro)
// ============================================================
__global__ void __launch_bounds__(256) xp_gemm_mma(
    const float* __restrict__ bih, const float* __restrict__ bhh)
{
  extern __shared__ __align__(128) char smg[];
  const uint32_t sbase = smem_u32(smg);
  float* eps = (float*)smg;
  const int tid  = threadIdx.x;
  const int wid  = tid >> 5;
  const int lane = tid & 31;
  const int bn = blockIdx.x * 128;   // data rows
  const int bm = blockIdx.y * 128;   // gate rows (0..1023)
  const int wm = (wid & 1) * 64;
  const int wn = (wid >> 1) * 32;

  MMA_MAINLOOP(g_xw, g_acat)

  {
    const int mo = (tid & 15) * 8;
    const int mg = bm + mo;
    const int gate = bm >> 8;
    const int ub = mg & 255;
    float bb[8];
    #pragma unroll
    for (int q=0;q<8;q++) bb[q] = bih[mg+q] + bhh[mg+q];
    #pragma unroll
    for (int it = 0; it < 8; it++) {
      int n = (tid >> 4) + it*16;
      int r = bn + n;
      if (r < NROWS) {
        const float* ep = eps + n*EPS_STRIDE + mo;
        float* op = g_xp + (size_t)r*G4 + ub*4 + gate;
        #pragma unroll
        for (int q=0;q<8;q++)
          op[q*4] = ep[q] + bb[q];
      }
    }
  }
}

// ============================================================
extern "C" void kernel_launch(void* const* d_in, const int* in_sizes, int n_in,
                              void* d_out, int out_size) {
  const float* thought = (const float*)d_in[0];
  const int*   captions= (const int*)  d_in[1];
  const float* emb_w   = (const float*)d_in[2];
  const float* w_ih0   = (const float*)d_in[3];
  const float* w_hh0   = (const float*)d_in[4];
  const float* b_ih0   = (const float*)d_in[5];
  const float* b_hh0   = (const float*)d_in[6];
  const float* w_ih1   = (const float*)d_in[7];
  const float* w_hh1   = (const float*)d_in[8];
  const float* b_ih1   = (const float*)d_in[9];
  const float* b_hh1   = (const float*)d_in[10];
  const float* gw1     = (const float*)d_in[11];
  const float* gb1     = (const float*)d_in[12];
  const float* gw2     = (const float*)d_in[13];
  const float* gb2     = (const float*)d_in[14];
  const float* ow      = (const float*)d_in[15];
  const float* ob      = (const float*)d_in[16];
  float* outp = (float*)d_out;

  static cudaStream_t s1 = nullptr;
  static cudaEvent_t ev0 = nullptr, ev1 = nullptr;
  if (!s1) {
    cudaStreamCreate(&s1);
    cudaEventCreateWithFlags(&ev0, cudaEventDisableTiming);
    cudaEventCreateWithFlags(&ev1, cudaEventDisableTiming);
    cudaFuncSetAttribute(out_gemm_mma, cudaFuncAttributeMaxDynamicSharedMemorySize, GSMEM3);
    cudaFuncSetAttribute(xp_gemm_mma,  cudaFuncAttributeMaxDynamicSharedMemorySize, XSMEM);
  }

  // fork: weight conversions overlap xp0 + scan0 (R10 layout)
  cudaEventRecord(ev0, 0);
  cudaStreamWaitEvent(s1, ev0, 0);
  wihcvt_kernel<<<G4, 256, 0, s1>>>(w_ih1);
  wcat_kernel<<<VOCAB, 256, 0, s1>>>(ow);
  cudaEventRecord(ev1, s1);

  xp0_kernel<<<NPAD/16, 256>>>(captions, emb_w, w_ih0, b_ih0, b_hh0);
  lstm_scan2<<<64, 256>>>(w_hh0, thought, 0);
  h1cvt_kernel<<<NPAD, 256>>>();
  cudaStreamWaitEvent(0, ev1, 0);
  {
    dim3 gx(NPAD/128, G4/128);                    // (32, 8)
    xp_gemm_mma<<<gx, 256, XSMEM>>>(b_ih1, b_hh1);
  }
  lstm_scan2<<<64, 256>>>(w_hh1, thought, 1);
  gateacat_kernel<<<512, 256>>>(gw1, gb1, gw2, gb2);
  dim3 gg(NPAD/128, VOCAB/128);                   // (32, 250)
  out_gemm_mma<<<gg, 256, GSMEM3>>>(ob, outp);
}

// round 14
// speedup vs baseline: 1.6688x; 1.0215x over previous
#include <cuda_runtime.h>
#include <cuda_bf16.h>
#include <cstdint>
#include <math.h>

#define STEPS 511
#define BATCH 8
#define HID   256
#define G4    1024
#define VOCAB 32000
#define NROWS (STEPS*BATCH)   // 4088
#define NPAD  4096
#define KCAT  768             // [hi | hi/lo split] concat K

// ---------------- scratch (no allocs allowed) ----------------
__device__ float g_xp[STEPS*BATCH*G4];                // gate-interleaved: [r][unit*4+gate]
__device__ float g_h2[STEPS*BATCH*HID];
__device__ __nv_bfloat16 g_wcat[(size_t)VOCAB*KCAT];  // 49 MB  out_w split
__device__ __nv_bfloat16 g_acat[(size_t)NPAD*KCAT];   // 6.3 MB (h1-split, then gated-h2-split)
__device__ __nv_bfloat16 g_xw[(size_t)G4*KCAT];       // 1.5 MB  w_ih1 split

__device__ __forceinline__ float sigmoidf_(float x){ return 1.0f/(1.0f + __expf(-x)); }

__device__ __forceinline__ uint32_t smem_u32(const void* p){
  return (uint32_t)__cvta_generic_to_shared(p);
}
__device__ __forceinline__ void mbar_init_(uint32_t a, uint32_t cnt){
  asm volatile("mbarrier.init.shared.b64 [%0], %1;" :: "r"(a), "r"(cnt) : "memory");
}
__device__ __forceinline__ void mbar_expect_tx_(uint32_t a, uint32_t bytes){
  asm volatile("mbarrier.arrive.expect_tx.shared.b64 _, [%0], %1;" :: "r"(a), "r"(bytes) : "memory");
}
__device__ __forceinline__ void mbar_wait_(uint32_t a, uint32_t phase){
  asm volatile("{\n\t.reg .pred P;\n\t"
    "WL_%=:\n\t"
    "mbarrier.try_wait.parity.acquire.cta.shared::cta.b64 P, [%0], %1, 0x989680;\n\t"
    "@P bra.uni WD_%=;\n\t"
    "bra.uni WL_%=;\n\t"
    "WD_%=:\n\t}" :: "r"(a), "r"(phase) : "memory");
}
__device__ __forceinline__ void st_async_b32_(uint32_t saddr, uint32_t smbar, uint32_t rank, uint32_t v){
  asm volatile("{\n\t.reg .b32 ra, rb;\n\t"
    "mapa.shared::cluster.u32 ra, %0, %2;\n\t"
    "mapa.shared::cluster.u32 rb, %1, %2;\n\t"
    "st.async.shared::cluster.mbarrier::complete_tx::bytes.b32 [ra], %3, [rb];\n\t}"
    :: "r"(saddr), "r"(smbar), "r"(rank), "r"(v) : "memory");
}
__device__ __forceinline__ void cluster_sync_(){
  asm volatile("barrier.cluster.arrive.aligned;" ::: "memory");
  asm volatile("barrier.cluster.wait.aligned;"   ::: "memory");
}
__device__ __forceinline__ void cp_async16_(uint32_t saddr, const void* gaddr){
  asm volatile("cp.async.cg.shared.global [%0], [%1], 16;" :: "r"(saddr), "l"(gaddr) : "memory");
}
#define CP_COMMIT() asm volatile("cp.async.commit_group;" ::: "memory")
#define CP_WAIT1()  asm volatile("cp.async.wait_group 1;" ::: "memory")
#define CP_WAIT0()  asm volatile("cp.async.wait_group 0;" ::: "memory")

__device__ __forceinline__ void ldsm_x4_(uint32_t* r, uint32_t addr){
  asm volatile("ldmatrix.sync.aligned.m8n8.x4.shared.b16 {%0,%1,%2,%3}, [%4];"
    : "=r"(r[0]), "=r"(r[1]), "=r"(r[2]), "=r"(r[3]) : "r"(addr));
}
__device__ __forceinline__ void mma16816_(float* d, const uint32_t* a, const uint32_t* b){
  asm volatile("mma.sync.aligned.m16n8k16.row.col.f32.bf16.bf16.f32 "
    "{%0,%1,%2,%3}, {%4,%5,%6,%7}, {%8,%9}, {%0,%1,%2,%3};"
    : "+f"(d[0]), "+f"(d[1]), "+f"(d[2]), "+f"(d[3])
    : "r"(a[0]), "r"(a[1]), "r"(a[2]), "r"(a[3]), "r"(b[0]), "r"(b[1]));
}
static __device__ __forceinline__ uint32_t sw128_(uint32_t b){ return b ^ ((b >> 3) & 0x70u); }

// ============================================================
// Layer-0 input projection (K=128): 16 rows per CTA (R13 exact)
// ============================================================
__global__ void __launch_bounds__(256) xp0_kernel(
    const int* __restrict__ captions, const float* __restrict__ emb_w,
    const float* __restrict__ W, const float* __restrict__ bias1,
    const float* __restrict__ bias2)
{
  __shared__ __align__(16) float As[16][128];
  const int tid = threadIdx.x;
  const int r0  = blockIdx.x * 16;

  for (int idx = tid; idx < 16*128; idx += 256) {
    int row = idx >> 7, k = idx & 127;
    int r = r0 + row;
    float v = 0.f;
    if (r < NROWS) {
      int b = r & 7, t = r >> 3;
      v = emb_w[(size_t)captions[b*512 + t] * 128 + k];
    }
    As[row][k] = v;
  }
  __syncthreads();

  float acc[4][16];
  #pragma unroll
  for (int i=0;i<4;i++)
    #pragma unroll
    for (int r=0;r<16;r++) acc[i][r]=0.f;

  const int c0 = tid;
  for (int k0 = 0; k0 < 128; k0 += 4) {
    float4 w0 = *(const float4*)&W[(size_t)(c0      )*128 + k0];
    float4 w1 = *(const float4*)&W[(size_t)(c0+256)*128 + k0];
    float4 w2 = *(const float4*)&W[(size_t)(c0+512)*128 + k0];
    float4 w3 = *(const float4*)&W[(size_t)(c0+768)*128 + k0];
    #pragma unroll
    for (int r=0;r<16;r++) {
      float4 a4 = *(const float4*)&As[r][k0];
      acc[0][r] = fmaf(w0.x, a4.x, acc[0][r]); acc[0][r] = fmaf(w0.y, a4.y, acc[0][r]);
      acc[0][r] = fmaf(w0.z, a4.z, acc[0][r]); acc[0][r] = fmaf(w0.w, a4.w, acc[0][r]);
      acc[1][r] = fmaf(w1.x, a4.x, acc[1][r]); acc[1][r] = fmaf(w1.y, a4.y, acc[1][r]);
      acc[1][r] = fmaf(w1.z, a4.z, acc[1][r]); acc[1][r] = fmaf(w1.w, a4.w, acc[1][r]);
      acc[2][r] = fmaf(w2.x, a4.x, acc[2][r]); acc[2][r] = fmaf(w2.y, a4.y, acc[2][r]);
      acc[2][r] = fmaf(w2.z, a4.z, acc[2][r]); acc[2][r] = fmaf(w2.w, a4.w, acc[2][r]);
      acc[3][r] = fmaf(w3.x, a4.x, acc[3][r]); acc[3][r] = fmaf(w3.y, a4.y, acc[3][r]);
      acc[3][r] = fmaf(w3.z, a4.z, acc[3][r]); acc[3][r] = fmaf(w3.w, a4.w, acc[3][r]);
    }
  }
  float bb[4];
  #pragma unroll
  for (int i=0;i<4;i++) bb[i] = bias1[c0+i*256] + bias2[c0+i*256];
  #pragma unroll
  for (int r=0;r<16;r++) {
    if (r0 + r < NROWS) {
      float4 o;
      o.x = acc[0][r]+bb[0]; o.y = acc[1][r]+bb[1];
      o.z = acc[2][r]+bb[2]; o.w = acc[3][r]+bb[3];
      *(float4*)&g_xp[(size_t)(r0+r)*G4 + c0*4] = o;
    }
  }
}

// ============================================================
// LSTM scan (R13 + layer-0 writes split-bf16 g_acat directly)
// ============================================================
__global__ __launch_bounds__(256,1) __cluster_dims__(8,1,1)
void lstm_scan2(const float* __restrict__ w_hh,
                const float* __restrict__ thought,
                int layer)
{
  __shared__ __align__(16) float h_s[2][HID];
  __shared__ __align__(8) unsigned long long mbar_sto[2];

  const int tid = threadIdx.x;
  const int b   = blockIdx.x >> 3;
  const int j   = blockIdx.x & 7;
  const int u   = tid >> 3;
  const int kp  = tid & 7;
  const int ug  = 32*j + u;

  float wreg[4][32];
  #pragma unroll
  for (int g=0; g<4; g++){
    const float* wp = w_hh + (size_t)(g*256 + ug)*HID + 32*kp;
    #pragma unroll
    for (int q=0;q<8;q++){
      float4 v = *(const float4*)(wp + 4*q);
      wreg[g][4*q+0]=v.x; wreg[g][4*q+1]=v.y; wreg[g][4*q+2]=v.z; wreg[g][4*q+3]=v.w;
    }
  }

  const uint32_t mb0 = smem_u32(&mbar_sto[0]);
  const uint32_t mb1 = smem_u32(&mbar_sto[1]);
  if (tid == 0) {
    mbar_init_(mb0, 1); mbar_init_(mb1, 1);
    mbar_expect_tx_(mb0, 1024); mbar_expect_tx_(mb1, 1024);
  }
  h_s[0][tid] = thought[b*HID + tid];
  __syncthreads();
  cluster_sync_();

  const uint32_t hs0 = smem_u32(&h_s[0][0]);
  const uint32_t hs1 = smem_u32(&h_s[1][0]);
  const bool owner = (kp == 0);
  float c = 0.f;

  for (int t = 0; t < STEPS; t++) {
    const int cur = t & 1;

    float4 xpv = make_float4(0.f,0.f,0.f,0.f);
    if (owner)
      xpv = *(const float4*)&g_xp[(size_t)(t*BATCH + b)*G4 + ug*4];

    if (t > 0) {
      mbar_wait_(cur ? mb1 : mb0, ((uint32_t)(t-1) >> 1) & 1u);
      if (tid == 0) mbar_expect_tx_(cur ? mb1 : mb0, 1024);
    }

    float a0=0.f,a1=0.f,a2=0.f,a3=0.f;
    const float4* h4 = (const float4*)&h_s[cur][32*kp];
    #pragma unroll
    for (int q=0;q<8;q++) {
      float4 hv = h4[q];
      a0=fmaf(wreg[0][4*q+0],hv.x,a0); a0=fmaf(wreg[0][4*q+1],hv.y,a0);
      a0=fmaf(wreg[0][4*q+2],hv.z,a0); a0=fmaf(wreg[0][4*q+3],hv.w,a0);
      a1=fmaf(wreg[1][4*q+0],hv.x,a1); a1=fmaf(wreg[1][4*q+1],hv.y,a1);
      a1=fmaf(wreg[1][4*q+2],hv.z,a1); a1=fmaf(wreg[1][4*q+3],hv.w,a1);
      a2=fmaf(wreg[2][4*q+0],hv.x,a2); a2=fmaf(wreg[2][4*q+1],hv.y,a2);
      a2=fmaf(wreg[2][4*q+2],hv.z,a2); a2=fmaf(wreg[2][4*q+3],hv.w,a2);
      a3=fmaf(wreg[3][4*q+0],hv.x,a3); a3=fmaf(wreg[3][4*q+1],hv.y,a3);
      a3=fmaf(wreg[3][4*q+2],hv.z,a3); a3=fmaf(wreg[3][4*q+3],hv.w,a3);
    }
    #pragma unroll
    for (int off=4; off>=1; off>>=1) {
      a0 += __shfl_xor_sync(0xffffffffu, a0, off);
      a1 += __shfl_xor_sync(0xffffffffu, a1, off);
      a2 += __shfl_xor_sync(0xffffffffu, a2, off);
      a3 += __shfl_xor_sync(0xffffffffu, a3, off);
    }

    if (owner) {
      float gi = sigmoidf_(a0 + xpv.x);
      float gf = sigmoidf_(a1 + xpv.y);
      float gg = 2.f*sigmoidf_(2.f*(a2 + xpv.z)) - 1.f;   // tanh
      float go = sigmoidf_(a3 + xpv.w);
      c = gf*c + gi*gg;
      float h = go * (2.f*sigmoidf_(2.f*c) - 1.f);
      if (layer == 0) {
        // write h1 directly as split-bf16 into g_acat [hi | lo | hi]
        __nv_bfloat16 hi = __float2bfloat16(h);
        __nv_bfloat16 lo = __float2bfloat16(h - __bfloat162float(hi));
        __nv_bfloat16* rp = g_acat + (size_t)(t*BATCH + b)*KCAT;
        rp[ug] = hi; rp[HID + ug] = lo; rp[2*HID + ug] = hi;
      } else {
        g_h2[(size_t)(t*BATCH+b)*HID + ug] = h;
      }
      if (t + 1 < STEPS) {
        uint32_t daddr = (cur ? hs0 : hs1) + (uint32_t)ug*4u;
        uint32_t dmb   = cur ? mb0 : mb1;
        uint32_t hv = __float_as_uint(h);
        #pragma unroll
        for (int p=0;p<8;p++) st_async_b32_(daddr, dmb, (uint32_t)p, hv);
      }
    }
  }
}

// ============================================================
// gate MLP fused with gated-h2 split-bf16 conversion (R13 exact)
// (also re-zeros g_acat pad rows every launch)
// ============================================================
__global__ void __launch_bounds__(256) gateacat_kernel(
    const float* __restrict__ gw1, const float* __restrict__ gb1,
    const float* __restrict__ gw2, const float* __restrict__ gb2)
{
  __shared__ __align__(16) float Hs[8][256];
  __shared__ float wp_s[8][8];
  __shared__ float gatev[8];
  const int tid = threadIdx.x;
  const int r0  = blockIdx.x * 8;

  if (r0 >= NROWS) {
    __nv_bfloat16 z = __float2bfloat16(0.f);
    #pragma unroll
    for (int row=0; row<8; row++){
      __nv_bfloat16* rp = g_acat + (size_t)(r0+row)*KCAT;
      rp[tid] = z; rp[HID+tid] = z; rp[2*HID+tid] = z;
    }
    return;
  }

  for (int idx = tid; idx < 8*256; idx += 256) {
    int row = idx >> 8, k = idx & 255;
    Hs[row][k] = g_h2[(size_t)(r0+row)*HID + k];
  }
  __syncthreads();

  float u[8];
  #pragma unroll
  for (int r=0;r<8;r++) u[r]=0.f;
  const float* wrow = gw1 + (size_t)tid*256;
  #pragma unroll 8
  for (int k0=0;k0<256;k0+=4){
    float4 w4 = *(const float4*)(wrow + k0);
    #pragma unroll
    for (int r=0;r<8;r++) {
      float4 a4 = *(const float4*)&Hs[r][k0];
      u[r] = fmaf(w4.x, a4.x, u[r]); u[r] = fmaf(w4.y, a4.y, u[r]);
      u[r] = fmaf(w4.z, a4.z, u[r]); u[r] = fmaf(w4.w, a4.w, u[r]);
    }
  }
  float g2 = gw2[tid], b1v = gb1[tid];
  float p[8];
  #pragma unroll
  for (int r=0;r<8;r++) p[r] = tanhf(u[r] + b1v) * g2;
  #pragma unroll
  for (int off=16; off>=1; off>>=1)
    #pragma unroll
    for (int r=0;r<8;r++) p[r] += __shfl_xor_sync(0xffffffffu, p[r], off);
  if ((tid & 31) == 0)
    #pragma unroll
    for (int r=0;r<8;r++) wp_s[tid>>5][r] = p[r];
  __syncthreads();
  if (tid < 8) {
    float s = 0.f;
    #pragma unroll
    for (int w=0;w<8;w++) s += wp_s[w][tid];
    gatev[tid] = sigmoidf_(s + gb2[0]);
  }
  __syncthreads();

  #pragma unroll
  for (int row=0; row<8; row++){
    float a = Hs[row][tid] * gatev[row];
    __nv_bfloat16 hi = __float2bfloat16(a);
    __nv_bfloat16 lo = __float2bfloat16(a - __bfloat162float(hi));
    __nv_bfloat16* rp = g_acat + (size_t)(r0+row)*KCAT;
    rp[tid] = hi; rp[HID+tid] = lo; rp[2*HID+tid] = hi;
  }
}

// ============================================================
// split-bf16 weight conversions (R13 exact)
// ============================================================
__global__ void __launch_bounds__(256) wcat_kernel(const float* __restrict__ ow){
  const int v = blockIdx.x, k = threadIdx.x;
  float w = ow[(size_t)v*HID + k];
  __nv_bfloat16 hi = __float2bfloat16(w);
  __nv_bfloat16 lo = __float2bfloat16(w - __bfloat162float(hi));
  __nv_bfloat16* row = g_wcat + (size_t)v*KCAT;
  row[k] = hi; row[HID + k] = hi; row[2*HID + k] = lo;
}

__global__ void __launch_bounds__(256) wihcvt_kernel(const float* __restrict__ wih){
  const int m = blockIdx.x, k = threadIdx.x;
  float w = wih[(size_t)m*HID + k];
  __nv_bfloat16 hi = __float2bfloat16(w);
  __nv_bfloat16 lo = __float2bfloat16(w - __bfloat162float(hi));
  __nv_bfloat16* row = g_xw + (size_t)m*KCAT;
  row[k] = hi; row[HID + k] = hi; row[2*HID + k] = lo;
}

// ============================================================
// 2-stage mma mainloop macro (R13 exact) — used by xp_gemm
// ============================================================
#define KC 64
#define NCHUNK (KCAT/KC)             // 12
#define STAGE_HALF 16384
#define STAGE_SZ   32768
#define EPS_STRIDE 132
#define XSMEM (2*STAGE_SZ + 4096)

#define MMA_MAINLOOP(WSRC, ASRC)                                                  \
  const int lrow = tid >> 1;                                                      \
  const int lseg4 = (tid & 1) * 4;                                                \
  _Pragma("unroll")                                                               \
  for (int c = 0; c < 2; c++) {                                                   \
    const uint32_t st = sbase + c*STAGE_SZ;                                       \
    const char* wg = (const char*)(WSRC) + ((size_t)(bm+lrow)*KCAT + c*KC)*2;     \
    const char* ag = (const char*)(ASRC) + ((size_t)(bn+lrow)*KCAT + c*KC)*2;     \
    _Pragma("unroll")                                                             \
    for (int q=0;q<4;q++){                                                        \
      uint32_t off = sw128_((uint32_t)(lrow*128 + (lseg4+q)*16));                 \
      cp_async16_(st + off, wg + (lseg4+q)*16);                                   \
      cp_async16_(st + STAGE_HALF + off, ag + (lseg4+q)*16);                      \
    }                                                                             \
    CP_COMMIT();                                                                  \
  }                                                                               \
  float acc[4][4][4];                                                             \
  _Pragma("unroll")                                                               \
  for (int i=0;i<4;i++)                                                           \
    _Pragma("unroll")                                                             \
    for (int jj=0;jj<4;jj++)                                                      \
      _Pragma("unroll")                                                           \
      for (int v=0;v<4;v++) acc[i][jj][v]=0.f;                                    \
  const uint32_t a_row = (uint32_t)(lane & 15);                                   \
  const uint32_t a_k16 = (uint32_t)((lane >> 4) * 16);                            \
  const uint32_t b_row = (uint32_t)((lane & 7) + ((lane & 16) >> 1));             \
  const uint32_t b_k16 = (uint32_t)((lane & 8) ? 16 : 0);                         \
  for (int c = 0; c < NCHUNK; c++) {                                              \
    CP_WAIT1();                                                                   \
    __syncthreads();                                                              \
    const uint32_t wbase = sbase + (c & 1)*STAGE_SZ;                              \
    const uint32_t abase = wbase + STAGE_HALF;                                    \
    _Pragma("unroll")                                                             \
    for (int k = 0; k < 4; k++) {                                                 \
      uint32_t af[4][4], bf[2][4];                                                \
      _Pragma("unroll")                                                           \
      for (int mt=0; mt<4; mt++)                                                  \
        ldsm_x4_(af[mt], wbase + sw128_((uint32_t)((wm + mt*16 + a_row)*128) + k*32 + a_k16)); \
      _Pragma("unroll")                                                           \
      for (int nt2=0; nt2<2; nt2++)                                               \
        ldsm_x4_(bf[nt2], abase + sw128_((uint32_t)((wn + nt2*16 + b_row)*128) + k*32 + b_k16)); \
      _Pragma("unroll")                                                           \
      for (int mt=0; mt<4; mt++)                                                  \
        _Pragma("unroll")                                                         \
        for (int nt=0; nt<4; nt++)                                                \
          mma16816_(acc[mt][nt], af[mt], &bf[nt>>1][(nt&1)*2]);                   \
    }                                                                             \
    __syncthreads();                                                              \
    if (c + 2 < NCHUNK) {                                                         \
      const uint32_t st = sbase + (c & 1)*STAGE_SZ;                               \
      const char* wg = (const char*)(WSRC) + ((size_t)(bm+lrow)*KCAT + (c+2)*KC)*2; \
      const char* ag = (const char*)(ASRC) + ((size_t)(bn+lrow)*KCAT + (c+2)*KC)*2; \
      _Pragma("unroll")                                                           \
      for (int q=0;q<4;q++){                                                      \
        uint32_t off = sw128_((uint32_t)(lrow*128 + (lseg4+q)*16));               \
        cp_async16_(st + off, wg + (lseg4+q)*16);                                 \
        cp_async16_(st + STAGE_HALF + off, ag + (lseg4+q)*16);                    \
      }                                                                           \
    }                                                                             \
    CP_COMMIT();                                                                  \
  }                                                                               \
  CP_WAIT0();                                                                     \
  __syncthreads();                                                                \
  {                                                                               \
    const int mq = lane >> 2;                                                     \
    const int nq = (lane & 3) * 2;                                                \
    _Pragma("unroll")                                                             \
    for (int mt=0; mt<4; mt++)                                                    \
      _Pragma("unroll")                                                           \
      for (int nt=0; nt<4; nt++){                                                 \
        int m0 = wm + mt*16 + mq;                                                 \
        int n0 = wn + nt*8 + nq;                                                  \
        eps[(n0  )*EPS_STRIDE + m0    ] = acc[mt][nt][0];                         \
        eps[(n0+1)*EPS_STRIDE + m0    ] = acc[mt][nt][1];                         \
        eps[(n0  )*EPS_STRIDE + m0 + 8] = acc[mt][nt][2];                         \
        eps[(n0+1)*EPS_STRIDE + m0 + 8] = acc[mt][nt][3];                         \
      }                                                                           \
  }                                                                               \
  __syncthreads();

// ============================================================
// xp1 GEMM (R13 exact)
// ============================================================
__global__ void __launch_bounds__(256) xp_gemm_mma(
    const float* __restrict__ bih, const float* __restrict__ bhh)
{
  extern __shared__ __align__(128) char smg[];
  const uint32_t sbase = smem_u32(smg);
  float* eps = (float*)smg;
  const int tid  = threadIdx.x;
  const int wid  = tid >> 5;
  const int lane = tid & 31;
  const int bn = blockIdx.x * 128;   // data rows
  const int bm = blockIdx.y * 128;   // gate rows (0..1023)
  const int wm = (wid & 1) * 64;
  const int wn = (wid >> 1) * 32;

  MMA_MAINLOOP(g_xw, g_acat)

  {
    const int mo = (tid & 15) * 8;
    const int mg = bm + mo;
    const int gate = bm >> 8;
    const int ub = mg & 255;
    float bb[8];
    #pragma unroll
    for (int q=0;q<8;q++) bb[q] = bih[mg+q] + bhh[mg+q];
    #pragma unroll
    for (int it = 0; it < 8; it++) {
      int n = (tid >> 4) + it*16;
      int r = bn + n;
      if (r < NROWS) {
        const float* ep = eps + n*EPS_STRIDE + mo;
        float* op = g_xp + (size_t)r*G4 + ub*4 + gate;
        #pragma unroll
        for (int q=0;q<8;q++)
          op[q*4] = ep[q] + bb[q];
      }
    }
  }
}

// ============================================================
// vocab GEMM: 256(vocab) x 128(rows) tile, 3-stage cp.async ring
// ============================================================
#define STAGE_W 32768                 // 256 rows x 128B
#define STAGE_A 16384                 // 128 rows x 128B
#define STAGE_SZV (STAGE_W+STAGE_A)   // 49152
#define GSMEMV (3*STAGE_SZV)          // 147456
#define EPSV 260                      // 260%32==4 -> conflict-free transpose

__global__ void __launch_bounds__(256) out_gemm_mma(
    const float* __restrict__ ob, float* __restrict__ outp)
{
  extern __shared__ __align__(128) char smg[];
  const uint32_t sbase = smem_u32(smg);
  float* eps = (float*)smg;
  const int tid  = threadIdx.x;
  const int wid  = tid >> 5;
  const int lane = tid & 31;
  const int bn = blockIdx.x * 128;    // data rows
  const int bm = blockIdx.y * 256;    // vocab rows
  const int wm = (wid & 1) * 128;
  const int wn = (wid >> 1) * 32;

  // loader: W 2048 segs (8/thread), A 1024 segs (4/thread)
  #pragma unroll
  for (int c = 0; c < 2; c++) {
    const uint32_t st = sbase + c*STAGE_SZV;
    #pragma unroll
    for (int q=0;q<8;q++){
      int s = q*256 + tid, row = s >> 3, seg = s & 7;
      cp_async16_(st + sw128_((uint32_t)(row*128 + seg*16)),
                  (const char*)g_wcat + ((size_t)(bm+row)*KCAT + c*KC)*2 + seg*16);
    }
    #pragma unroll
    for (int q=0;q<4;q++){
      int s = q*256 + tid, row = s >> 3, seg = s & 7;
      cp_async16_(st + STAGE_W + sw128_((uint32_t)(row*128 + seg*16)),
                  (const char*)g_acat + ((size_t)(bn+row)*KCAT + c*KC)*2 + seg*16);
    }
    CP_COMMIT();
  }

  float acc[8][4][4];
  #pragma unroll
  for (int i=0;i<8;i++)
    #pragma unroll
    for (int jj=0;jj<4;jj++)
      #pragma unroll
      for (int v=0;v<4;v++) acc[i][jj][v]=0.f;
  const uint32_t a_row = (uint32_t)(lane & 15);
  const uint32_t a_k16 = (uint32_t)((lane >> 4) * 16);
  const uint32_t b_row = (uint32_t)((lane & 7) + ((lane & 16) >> 1));
  const uint32_t b_k16 = (uint32_t)((lane & 8) ? 16 : 0);

  int s = 0, sw = 2;
  for (int c = 0; c < NCHUNK; c++) {
    CP_WAIT1();
    __syncthreads();
    if (c + 2 < NCHUNK) {
      const uint32_t st = sbase + sw*STAGE_SZV;
      #pragma unroll
      for (int q=0;q<8;q++){
        int sg = q*256 + tid, row = sg >> 3, seg = sg & 7;
        cp_async16_(st + sw128_((uint32_t)(row*128 + seg*16)),
                    (const char*)g_wcat + ((size_t)(bm+row)*KCAT + (c+2)*KC)*2 + seg*16);
      }
      #pragma unroll
      for (int q=0;q<4;q++){
        int sg = q*256 + tid, row = sg >> 3, seg = sg & 7;
        cp_async16_(st + STAGE_W + sw128_((uint32_t)(row*128 + seg*16)),
                    (const char*)g_acat + ((size_t)(bn+row)*KCAT + (c+2)*KC)*2 + seg*16);
      }
    }
    CP_COMMIT();
    const uint32_t wbase = sbase + s*STAGE_SZV;
    const uint32_t abase = wbase + STAGE_W;
    #pragma unroll
    for (int k = 0; k < 4; k++) {
      uint32_t af[8][4], bf[2][4];
      #pragma unroll
      for (int mt=0; mt<8; mt++)
        ldsm_x4_(af[mt], wbase + sw128_((uint32_t)((wm + mt*16 + a_row)*128) + k*32 + a_k16));
      #pragma unroll
      for (int nt2=0; nt2<2; nt2++)
        ldsm_x4_(bf[nt2], abase + sw128_((uint32_t)((wn + nt2*16 + b_row)*128) + k*32 + b_k16));
      #pragma unroll
      for (int mt=0; mt<8; mt++)
        #pragma unroll
        for (int nt=0; nt<4; nt++)
          mma16816_(acc[mt][nt], af[mt], &bf[nt>>1][(nt&1)*2]);
    }
    s  = (s  + 1 == 3) ? 0 : s  + 1;
    sw = (sw + 1 == 3) ? 0 : sw + 1;
  }
  CP_WAIT0();
  __syncthreads();   // all mma smem reads done before eps overlay
  {
    const int mq = lane >> 2;
    const int nq = (lane & 3) * 2;
    #pragma unroll
    for (int mt=0; mt<8; mt++)
      #pragma unroll
      for (int nt=0; nt<4; nt++){
        int m0 = wm + mt*16 + mq;
        int n0 = wn + nt*8 + nq;
        eps[(n0  )*EPSV + m0    ] = acc[mt][nt][0];
        eps[(n0+1)*EPSV + m0    ] = acc[mt][nt][1];
        eps[(n0  )*EPSV + m0 + 8] = acc[mt][nt][2];
        eps[(n0+1)*EPSV + m0 + 8] = acc[mt][nt][3];
      }
  }
  __syncthreads();
  {
    const int mo = (tid & 31) * 8;     // 256 vocab / 8 per thread-group
    const int vg = bm + mo;
    float4 ob0 = *(const float4*)&ob[vg];
    float4 ob1 = *(const float4*)&ob[vg+4];
    #pragma unroll
    for (int it = 0; it < 16; it++) {
      int n = (tid >> 5) + it*8;
      int r = bn + n;
      if (r < NROWS) {
        const float* ep = eps + n*EPSV + mo;
        float4 v0 = *(const float4*)ep;
        float4 v1 = *(const float4*)(ep+4);
        v0.x+=ob0.x; v0.y+=ob0.y; v0.z+=ob0.z; v0.w+=ob0.w;
        v1.x+=ob1.x; v1.y+=ob1.y; v1.z+=ob1.z; v1.w+=ob1.w;
        float* op = outp + (size_t)((r & 7)*STEPS + (r >> 3))*VOCAB + vg;
        *(float4*)op     = v0;
        *(float4*)(op+4) = v1;
      }
    }
  }
}

// ============================================================
extern "C" void kernel_launch(void* const* d_in, const int* in_sizes, int n_in,
                              void* d_out, int out_size) {
  const float* thought = (const float*)d_in[0];
  const int*   captions= (const int*)  d_in[1];
  const float* emb_w   = (const float*)d_in[2];
  const float* w_ih0   = (const float*)d_in[3];
  const float* w_hh0   = (const float*)d_in[4];
  const float* b_ih0   = (const float*)d_in[5];
  const float* b_hh0   = (const float*)d_in[6];
  const float* w_ih1   = (const float*)d_in[7];
  const float* w_hh1   = (const float*)d_in[8];
  const float* b_ih1   = (const float*)d_in[9];
  const float* b_hh1   = (const float*)d_in[10];
  const float* gw1     = (const float*)d_in[11];
  const float* gb1     = (const float*)d_in[12];
  const float* gw2     = (const float*)d_in[13];
  const float* gb2     = (const float*)d_in[14];
  const float* ow      = (const float*)d_in[15];
  const float* ob      = (const float*)d_in[16];
  float* outp = (float*)d_out;

  static cudaStream_t s1 = nullptr;
  static cudaEvent_t ev0 = nullptr, ev1 = nullptr;
  if (!s1) {
    cudaStreamCreate(&s1);
    cudaEventCreateWithFlags(&ev0, cudaEventDisableTiming);
    cudaEventCreateWithFlags(&ev1, cudaEventDisableTiming);
    cudaFuncSetAttribute(out_gemm_mma, cudaFuncAttributeMaxDynamicSharedMemorySize, GSMEMV);
    cudaFuncSetAttribute(xp_gemm_mma,  cudaFuncAttributeMaxDynamicSharedMemorySize, XSMEM);
  }

  // fork: weight conversions overlap xp0 + scan0
  cudaEventRecord(ev0, 0);
  cudaStreamWaitEvent(s1, ev0, 0);
  wihcvt_kernel<<<G4, 256, 0, s1>>>(w_ih1);
  wcat_kernel<<<VOCAB, 256, 0, s1>>>(ow);
  cudaEventRecord(ev1, s1);

  xp0_kernel<<<NPAD/16, 256>>>(captions, emb_w, w_ih0, b_ih0, b_hh0);
  lstm_scan2<<<64, 256>>>(w_hh0, thought, 0);   // writes h1 split into g_acat
  cudaStreamWaitEvent(0, ev1, 0);
  {
    dim3 gx(NPAD/128, G4/128);                    // (32, 8)
    xp_gemm_mma<<<gx, 256, XSMEM>>>(b_ih1, b_hh1);
  }
  lstm_scan2<<<64, 256>>>(w_hh1, thought, 1);
  gateacat_kernel<<<512, 256>>>(gw1, gb1, gw2, gb2);
  dim3 gg(NPAD/128, VOCAB/256);                   // (32, 125)
  out_gemm_mma<<<gg, 256, GSMEMV>>>(ob, outp);
}

// round 15
// speedup vs baseline: 1.7082x; 1.0236x over previous
#include <cuda_runtime.h>
#include <cuda_bf16.h>
#include <cstdint>
#include <math.h>

#define STEPS 511
#define BATCH 8
#define HID   256
#define G4    1024
#define VOCAB 32000
#define NROWS (STEPS*BATCH)   // 4088
#define NPAD  4096
#define KCAT  768             // [hi | hi/lo split] concat K

// ---------------- scratch (no allocs allowed) ----------------
__device__ float g_xp[STEPS*BATCH*G4];                // gate-interleaved: [r][unit*4+gate]
__device__ float g_h2[STEPS*BATCH*HID];
__device__ __nv_bfloat16 g_wcat[(size_t)VOCAB*KCAT];  // 49 MB  out_w split
__device__ __nv_bfloat16 g_acat[(size_t)NPAD*KCAT];   // 6.3 MB (h1-split, then gated-h2-split)
__device__ __nv_bfloat16 g_xw[(size_t)G4*KCAT];       // 1.5 MB  w_ih1 split

__device__ __forceinline__ float sigmoidf_(float x){ return 1.0f/(1.0f + __expf(-x)); }

__device__ __forceinline__ uint32_t smem_u32(const void* p){
  return (uint32_t)__cvta_generic_to_shared(p);
}
__device__ __forceinline__ void mbar_init_(uint32_t a, uint32_t cnt){
  asm volatile("mbarrier.init.shared.b64 [%0], %1;" :: "r"(a), "r"(cnt) : "memory");
}
__device__ __forceinline__ void mbar_expect_tx_(uint32_t a, uint32_t bytes){
  asm volatile("mbarrier.arrive.expect_tx.shared.b64 _, [%0], %1;" :: "r"(a), "r"(bytes) : "memory");
}
__device__ __forceinline__ void mbar_wait_(uint32_t a, uint32_t phase){
  asm volatile("{\n\t.reg .pred P;\n\t"
    "WL_%=:\n\t"
    "mbarrier.try_wait.parity.acquire.cta.shared::cta.b64 P, [%0], %1, 0x989680;\n\t"
    "@P bra.uni WD_%=;\n\t"
    "bra.uni WL_%=;\n\t"
    "WD_%=:\n\t}" :: "r"(a), "r"(phase) : "memory");
}
__device__ __forceinline__ void st_async_b32_(uint32_t saddr, uint32_t smbar, uint32_t rank, uint32_t v){
  asm volatile("{\n\t.reg .b32 ra, rb;\n\t"
    "mapa.shared::cluster.u32 ra, %0, %2;\n\t"
    "mapa.shared::cluster.u32 rb, %1, %2;\n\t"
    "st.async.shared::cluster.mbarrier::complete_tx::bytes.b32 [ra], %3, [rb];\n\t}"
    :: "r"(saddr), "r"(smbar), "r"(rank), "r"(v) : "memory");
}
__device__ __forceinline__ void cluster_sync_(){
  asm volatile("barrier.cluster.arrive.aligned;" ::: "memory");
  asm volatile("barrier.cluster.wait.aligned;"   ::: "memory");
}
__device__ __forceinline__ void cp_async16_(uint32_t saddr, const void* gaddr){
  asm volatile("cp.async.cg.shared.global [%0], [%1], 16;" :: "r"(saddr), "l"(gaddr) : "memory");
}
#define CP_COMMIT() asm volatile("cp.async.commit_group;" ::: "memory")
#define CP_WAIT1()  asm volatile("cp.async.wait_group 1;" ::: "memory")
#define CP_WAIT0()  asm volatile("cp.async.wait_group 0;" ::: "memory")

__device__ __forceinline__ void ldsm_x4_(uint32_t* r, uint32_t addr){
  asm volatile("ldmatrix.sync.aligned.m8n8.x4.shared.b16 {%0,%1,%2,%3}, [%4];"
    : "=r"(r[0]), "=r"(r[1]), "=r"(r[2]), "=r"(r[3]) : "r"(addr));
}
__device__ __forceinline__ void mma16816_(float* d, const uint32_t* a, const uint32_t* b){
  asm volatile("mma.sync.aligned.m16n8k16.row.col.f32.bf16.bf16.f32 "
    "{%0,%1,%2,%3}, {%4,%5,%6,%7}, {%8,%9}, {%0,%1,%2,%3};"
    : "+f"(d[0]), "+f"(d[1]), "+f"(d[2]), "+f"(d[3])
    : "r"(a[0]), "r"(a[1]), "r"(a[2]), "r"(a[3]), "r"(b[0]), "r"(b[1]));
}
static __device__ __forceinline__ uint32_t sw128_(uint32_t b){ return b ^ ((b >> 3) & 0x70u); }

// ============================================================
// Layer-0 input projection (K=128): 16 rows per CTA (R14 exact)
// ============================================================
__global__ void __launch_bounds__(256) xp0_kernel(
    const int* __restrict__ captions, const float* __restrict__ emb_w,
    const float* __restrict__ W, const float* __restrict__ bias1,
    const float* __restrict__ bias2)
{
  __shared__ __align__(16) float As[16][128];
  const int tid = threadIdx.x;
  const int r0  = blockIdx.x * 16;

  for (int idx = tid; idx < 16*128; idx += 256) {
    int row = idx >> 7, k = idx & 127;
    int r = r0 + row;
    float v = 0.f;
    if (r < NROWS) {
      int b = r & 7, t = r >> 3;
      v = emb_w[(size_t)captions[b*512 + t] * 128 + k];
    }
    As[row][k] = v;
  }
  __syncthreads();

  float acc[4][16];
  #pragma unroll
  for (int i=0;i<4;i++)
    #pragma unroll
    for (int r=0;r<16;r++) acc[i][r]=0.f;

  const int c0 = tid;
  for (int k0 = 0; k0 < 128; k0 += 4) {
    float4 w0 = *(const float4*)&W[(size_t)(c0      )*128 + k0];
    float4 w1 = *(const float4*)&W[(size_t)(c0+256)*128 + k0];
    float4 w2 = *(const float4*)&W[(size_t)(c0+512)*128 + k0];
    float4 w3 = *(const float4*)&W[(size_t)(c0+768)*128 + k0];
    #pragma unroll
    for (int r=0;r<16;r++) {
      float4 a4 = *(const float4*)&As[r][k0];
      acc[0][r] = fmaf(w0.x, a4.x, acc[0][r]); acc[0][r] = fmaf(w0.y, a4.y, acc[0][r]);
      acc[0][r] = fmaf(w0.z, a4.z, acc[0][r]); acc[0][r] = fmaf(w0.w, a4.w, acc[0][r]);
      acc[1][r] = fmaf(w1.x, a4.x, acc[1][r]); acc[1][r] = fmaf(w1.y, a4.y, acc[1][r]);
      acc[1][r] = fmaf(w1.z, a4.z, acc[1][r]); acc[1][r] = fmaf(w1.w, a4.w, acc[1][r]);
      acc[2][r] = fmaf(w2.x, a4.x, acc[2][r]); acc[2][r] = fmaf(w2.y, a4.y, acc[2][r]);
      acc[2][r] = fmaf(w2.z, a4.z, acc[2][r]); acc[2][r] = fmaf(w2.w, a4.w, acc[2][r]);
      acc[3][r] = fmaf(w3.x, a4.x, acc[3][r]); acc[3][r] = fmaf(w3.y, a4.y, acc[3][r]);
      acc[3][r] = fmaf(w3.z, a4.z, acc[3][r]); acc[3][r] = fmaf(w3.w, a4.w, acc[3][r]);
    }
  }
  float bb[4];
  #pragma unroll
  for (int i=0;i<4;i++) bb[i] = bias1[c0+i*256] + bias2[c0+i*256];
  #pragma unroll
  for (int r=0;r<16;r++) {
    if (r0 + r < NROWS) {
      float4 o;
      o.x = acc[0][r]+bb[0]; o.y = acc[1][r]+bb[1];
      o.z = acc[2][r]+bb[2]; o.w = acc[3][r]+bb[3];
      *(float4*)&g_xp[(size_t)(r0+r)*G4 + c0*4] = o;
    }
  }
}

// ============================================================
// LSTM scan: all lanes compute activation redundantly; lane kp
// sends to rank kp (parallel st.async, 1 per lane).
// ============================================================
__global__ __launch_bounds__(256,1) __cluster_dims__(8,1,1)
void lstm_scan2(const float* __restrict__ w_hh,
                const float* __restrict__ thought,
                int layer)
{
  __shared__ __align__(16) float h_s[2][HID];
  __shared__ __align__(8) unsigned long long mbar_sto[2];

  const int tid = threadIdx.x;
  const int b   = blockIdx.x >> 3;
  const int j   = blockIdx.x & 7;
  const int u   = tid >> 3;
  const int kp  = tid & 7;
  const int ug  = 32*j + u;

  float wreg[4][32];
  #pragma unroll
  for (int g=0; g<4; g++){
    const float* wp = w_hh + (size_t)(g*256 + ug)*HID + 32*kp;
    #pragma unroll
    for (int q=0;q<8;q++){
      float4 v = *(const float4*)(wp + 4*q);
      wreg[g][4*q+0]=v.x; wreg[g][4*q+1]=v.y; wreg[g][4*q+2]=v.z; wreg[g][4*q+3]=v.w;
    }
  }

  const uint32_t mb0 = smem_u32(&mbar_sto[0]);
  const uint32_t mb1 = smem_u32(&mbar_sto[1]);
  if (tid == 0) {
    mbar_init_(mb0, 1); mbar_init_(mb1, 1);
    mbar_expect_tx_(mb0, 1024); mbar_expect_tx_(mb1, 1024);
  }
  h_s[0][tid] = thought[b*HID + tid];
  __syncthreads();
  cluster_sync_();

  const uint32_t hs0 = smem_u32(&h_s[0][0]);
  const uint32_t hs1 = smem_u32(&h_s[1][0]);
  const bool owner = (kp == 0);
  float c = 0.f;

  for (int t = 0; t < STEPS; t++) {
    const int cur = t & 1;

    // broadcast xp load: same address across the 8 kp lanes
    float4 xpv = *(const float4*)&g_xp[(size_t)(t*BATCH + b)*G4 + ug*4];

    if (t > 0) {
      mbar_wait_(cur ? mb1 : mb0, ((uint32_t)(t-1) >> 1) & 1u);
      if (tid == 0) mbar_expect_tx_(cur ? mb1 : mb0, 1024);
    }

    float a0=0.f,a1=0.f,a2=0.f,a3=0.f;
    const float4* h4 = (const float4*)&h_s[cur][32*kp];
    #pragma unroll
    for (int q=0;q<8;q++) {
      float4 hv = h4[q];
      a0=fmaf(wreg[0][4*q+0],hv.x,a0); a0=fmaf(wreg[0][4*q+1],hv.y,a0);
      a0=fmaf(wreg[0][4*q+2],hv.z,a0); a0=fmaf(wreg[0][4*q+3],hv.w,a0);
      a1=fmaf(wreg[1][4*q+0],hv.x,a1); a1=fmaf(wreg[1][4*q+1],hv.y,a1);
      a1=fmaf(wreg[1][4*q+2],hv.z,a1); a1=fmaf(wreg[1][4*q+3],hv.w,a1);
      a2=fmaf(wreg[2][4*q+0],hv.x,a2); a2=fmaf(wreg[2][4*q+1],hv.y,a2);
      a2=fmaf(wreg[2][4*q+2],hv.z,a2); a2=fmaf(wreg[2][4*q+3],hv.w,a2);
      a3=fmaf(wreg[3][4*q+0],hv.x,a3); a3=fmaf(wreg[3][4*q+1],hv.y,a3);
      a3=fmaf(wreg[3][4*q+2],hv.z,a3); a3=fmaf(wreg[3][4*q+3],hv.w,a3);
    }
    #pragma unroll
    for (int off=4; off>=1; off>>=1) {
      a0 += __shfl_xor_sync(0xffffffffu, a0, off);
      a1 += __shfl_xor_sync(0xffffffffu, a1, off);
      a2 += __shfl_xor_sync(0xffffffffu, a2, off);
      a3 += __shfl_xor_sync(0xffffffffu, a3, off);
    }

    // all lanes compute the identical activation (bit-identical inputs)
    float gi = sigmoidf_(a0 + xpv.x);
    float gf = sigmoidf_(a1 + xpv.y);
    float gg = 2.f*sigmoidf_(2.f*(a2 + xpv.z)) - 1.f;   // tanh
    float go = sigmoidf_(a3 + xpv.w);
    c = gf*c + gi*gg;
    float h = go * (2.f*sigmoidf_(2.f*c) - 1.f);
    uint32_t hv = __float_as_uint(h);

    // parallel h-exchange: lane kp sends this unit's h to rank kp
    if (t + 1 < STEPS) {
      uint32_t daddr = (cur ? hs0 : hs1) + (uint32_t)ug*4u;
      uint32_t dmb   = cur ? mb0 : mb1;
      st_async_b32_(daddr, dmb, (uint32_t)kp, hv);
    }

    if (owner) {
      if (layer == 0) {
        __nv_bfloat16 hi = __float2bfloat16(h);
        __nv_bfloat16 lo = __float2bfloat16(h - __bfloat162float(hi));
        __nv_bfloat16* rp = g_acat + (size_t)(t*BATCH + b)*KCAT;
        rp[ug] = hi; rp[HID + ug] = lo; rp[2*HID + ug] = hi;
      } else {
        g_h2[(size_t)(t*BATCH+b)*HID + ug] = h;
      }
    }
  }
}

// ============================================================
// gate MLP fused with gated-h2 split-bf16 conversion (R14 exact)
// ============================================================
__global__ void __launch_bounds__(256) gateacat_kernel(
    const float* __restrict__ gw1, const float* __restrict__ gb1,
    const float* __restrict__ gw2, const float* __restrict__ gb2)
{
  __shared__ __align__(16) float Hs[8][256];
  __shared__ float wp_s[8][8];
  __shared__ float gatev[8];
  const int tid = threadIdx.x;
  const int r0  = blockIdx.x * 8;

  if (r0 >= NROWS) {
    __nv_bfloat16 z = __float2bfloat16(0.f);
    #pragma unroll
    for (int row=0; row<8; row++){
      __nv_bfloat16* rp = g_acat + (size_t)(r0+row)*KCAT;
      rp[tid] = z; rp[HID+tid] = z; rp[2*HID+tid] = z;
    }
    return;
  }

  for (int idx = tid; idx < 8*256; idx += 256) {
    int row = idx >> 8, k = idx & 255;
    Hs[row][k] = g_h2[(size_t)(r0+row)*HID + k];
  }
  __syncthreads();

  float u[8];
  #pragma unroll
  for (int r=0;r<8;r++) u[r]=0.f;
  const float* wrow = gw1 + (size_t)tid*256;
  #pragma unroll 8
  for (int k0=0;k0<256;k0+=4){
    float4 w4 = *(const float4*)(wrow + k0);
    #pragma unroll
    for (int r=0;r<8;r++) {
      float4 a4 = *(const float4*)&Hs[r][k0];
      u[r] = fmaf(w4.x, a4.x, u[r]); u[r] = fmaf(w4.y, a4.y, u[r]);
      u[r] = fmaf(w4.z, a4.z, u[r]); u[r] = fmaf(w4.w, a4.w, u[r]);
    }
  }
  float g2 = gw2[tid], b1v = gb1[tid];
  float p[8];
  #pragma unroll
  for (int r=0;r<8;r++) p[r] = tanhf(u[r] + b1v) * g2;
  #pragma unroll
  for (int off=16; off>=1; off>>=1)
    #pragma unroll
    for (int r=0;r<8;r++) p[r] += __shfl_xor_sync(0xffffffffu, p[r], off);
  if ((tid & 31) == 0)
    #pragma unroll
    for (int r=0;r<8;r++) wp_s[tid>>5][r] = p[r];
  __syncthreads();
  if (tid < 8) {
    float s = 0.f;
    #pragma unroll
    for (int w=0;w<8;w++) s += wp_s[w][tid];
    gatev[tid] = sigmoidf_(s + gb2[0]);
  }
  __syncthreads();

  #pragma unroll
  for (int row=0; row<8; row++){
    float a = Hs[row][tid] * gatev[row];
    __nv_bfloat16 hi = __float2bfloat16(a);
    __nv_bfloat16 lo = __float2bfloat16(a - __bfloat162float(hi));
    __nv_bfloat16* rp = g_acat + (size_t)(r0+row)*KCAT;
    rp[tid] = hi; rp[HID+tid] = lo; rp[2*HID+tid] = hi;
  }
}

// ============================================================
// split-bf16 weight conversions (R14 exact)
// ============================================================
__global__ void __launch_bounds__(256) wcat_kernel(const float* __restrict__ ow){
  const int v = blockIdx.x, k = threadIdx.x;
  float w = ow[(size_t)v*HID + k];
  __nv_bfloat16 hi = __float2bfloat16(w);
  __nv_bfloat16 lo = __float2bfloat16(w - __bfloat162float(hi));
  __nv_bfloat16* row = g_wcat + (size_t)v*KCAT;
  row[k] = hi; row[HID + k] = hi; row[2*HID + k] = lo;
}

__global__ void __launch_bounds__(256) wihcvt_kernel(const float* __restrict__ wih){
  const int m = blockIdx.x, k = threadIdx.x;
  float w = wih[(size_t)m*HID + k];
  __nv_bfloat16 hi = __float2bfloat16(w);
  __nv_bfloat16 lo = __float2bfloat16(w - __bfloat162float(hi));
  __nv_bfloat16* row = g_xw + (size_t)m*KCAT;
  row[k] = hi; row[HID + k] = hi; row[2*HID + k] = lo;
}

// ============================================================
// 2-stage mma mainloop macro (R14 exact) — used by xp_gemm
// ============================================================
#define KC 64
#define NCHUNK (KCAT/KC)             // 12
#define STAGE_HALF 16384
#define STAGE_SZ   32768
#define EPS_STRIDE 132
#define XSMEM (2*STAGE_SZ + 4096)

#define MMA_MAINLOOP(WSRC, ASRC)                                                  \
  const int lrow = tid >> 1;                                                      \
  const int lseg4 = (tid & 1) * 4;                                                \
  _Pragma("unroll")                                                               \
  for (int c = 0; c < 2; c++) {                                                   \
    const uint32_t st = sbase + c*STAGE_SZ;                                       \
    const char* wg = (const char*)(WSRC) + ((size_t)(bm+lrow)*KCAT + c*KC)*2;     \
    const char* ag = (const char*)(ASRC) + ((size_t)(bn+lrow)*KCAT + c*KC)*2;     \
    _Pragma("unroll")                                                             \
    for (int q=0;q<4;q++){                                                        \
      uint32_t off = sw128_((uint32_t)(lrow*128 + (lseg4+q)*16));                 \
      cp_async16_(st + off, wg + (lseg4+q)*16);                                   \
      cp_async16_(st + STAGE_HALF + off, ag + (lseg4+q)*16);                      \
    }                                                                             \
    CP_COMMIT();                                                                  \
  }                                                                               \
  float acc[4][4][4];                                                             \
  _Pragma("unroll")                                                               \
  for (int i=0;i<4;i++)                                                           \
    _Pragma("unroll")                                                             \
    for (int jj=0;jj<4;jj++)                                                      \
      _Pragma("unroll")                                                           \
      for (int v=0;v<4;v++) acc[i][jj][v]=0.f;                                    \
  const uint32_t a_row = (uint32_t)(lane & 15);                                   \
  const uint32_t a_k16 = (uint32_t)((lane >> 4) * 16);                            \
  const uint32_t b_row = (uint32_t)((lane & 7) + ((lane & 16) >> 1));             \
  const uint32_t b_k16 = (uint32_t)((lane & 8) ? 16 : 0);                         \
  for (int c = 0; c < NCHUNK; c++) {                                              \
    CP_WAIT1();                                                                   \
    __syncthreads();                                                              \
    const uint32_t wbase = sbase + (c & 1)*STAGE_SZ;                              \
    const uint32_t abase = wbase + STAGE_HALF;                                    \
    _Pragma("unroll")                                                             \
    for (int k = 0; k < 4; k++) {                                                 \
      uint32_t af[4][4], bf[2][4];                                                \
      _Pragma("unroll")                                                           \
      for (int mt=0; mt<4; mt++)                                                  \
        ldsm_x4_(af[mt], wbase + sw128_((uint32_t)((wm + mt*16 + a_row)*128) + k*32 + a_k16)); \
      _Pragma("unroll")                                                           \
      for (int nt2=0; nt2<2; nt2++)                                               \
        ldsm_x4_(bf[nt2], abase + sw128_((uint32_t)((wn + nt2*16 + b_row)*128) + k*32 + b_k16)); \
      _Pragma("unroll")                                                           \
      for (int mt=0; mt<4; mt++)                                                  \
        _Pragma("unroll")                                                         \
        for (int nt=0; nt<4; nt++)                                                \
          mma16816_(acc[mt][nt], af[mt], &bf[nt>>1][(nt&1)*2]);                   \
    }                                                                             \
    __syncthreads();                                                              \
    if (c + 2 < NCHUNK) {                                                         \
      const uint32_t st = sbase + (c & 1)*STAGE_SZ;                               \
      const char* wg = (const char*)(WSRC) + ((size_t)(bm+lrow)*KCAT + (c+2)*KC)*2; \
      const char* ag = (const char*)(ASRC) + ((size_t)(bn+lrow)*KCAT + (c+2)*KC)*2; \
      _Pragma("unroll")                                                           \
      for (int q=0;q<4;q++){                                                      \
        uint32_t off = sw128_((uint32_t)(lrow*128 + (lseg4+q)*16));               \
        cp_async16_(st + off, wg + (lseg4+q)*16);                                 \
        cp_async16_(st + STAGE_HALF + off, ag + (lseg4+q)*16);                    \
      }                                                                           \
    }                                                                             \
    CP_COMMIT();                                                                  \
  }                                                                               \
  CP_WAIT0();                                                                     \
  __syncthreads();                                                                \
  {                                                                               \
    const int mq = lane >> 2;                                                     \
    const int nq = (lane & 3) * 2;                                                \
    _Pragma("unroll")                                                             \
    for (int mt=0; mt<4; mt++)                                                    \
      _Pragma("unroll")                                                           \
      for (int nt=0; nt<4; nt++){                                                 \
        int m0 = wm + mt*16 + mq;                                                 \
        int n0 = wn + nt*8 + nq;                                                  \
        eps[(n0  )*EPS_STRIDE + m0    ] = acc[mt][nt][0];                         \
        eps[(n0+1)*EPS_STRIDE + m0    ] = acc[mt][nt][1];                         \
        eps[(n0  )*EPS_STRIDE + m0 + 8] = acc[mt][nt][2];                         \
        eps[(n0+1)*EPS_STRIDE + m0 + 8] = acc[mt][nt][3];                         \
      }                                                                           \
  }                                                                               \
  __syncthreads();

// ============================================================
// xp1 GEMM (R14 exact)
// ============================================================
__global__ void __launch_bounds__(256) xp_gemm_mma(
    const float* __restrict__ bih, const float* __restrict__ bhh)
{
  extern __shared__ __align__(128) char smg[];
  const uint32_t sbase = smem_u32(smg);
  float* eps = (float*)smg;
  const int tid  = threadIdx.x;
  const int wid  = tid >> 5;
  const int lane = tid & 31;
  const int bn = blockIdx.x * 128;   // data rows
  const int bm = blockIdx.y * 128;   // gate rows (0..1023)
  const int wm = (wid & 1) * 64;
  const int wn = (wid >> 1) * 32;

  MMA_MAINLOOP(g_xw, g_acat)

  {
    const int mo = (tid & 15) * 8;
    const int mg = bm + mo;
    const int gate = bm >> 8;
    const int ub = mg & 255;
    float bb[8];
    #pragma unroll
    for (int q=0;q<8;q++) bb[q] = bih[mg+q] + bhh[mg+q];
    #pragma unroll
    for (int it = 0; it < 8; it++) {
      int n = (tid >> 4) + it*16;
      int r = bn + n;
      if (r < NROWS) {
        const float* ep = eps + n*EPS_STRIDE + mo;
        float* op = g_xp + (size_t)r*G4 + ub*4 + gate;
        #pragma unroll
        for (int q=0;q<8;q++)
          op[q*4] = ep[q] + bb[q];
      }
    }
  }
}

// ============================================================
// vocab GEMM: 256(vocab) x 128(rows) tile, 3-stage ring (R14 exact)
// ============================================================
#define STAGE_W 32768
#define STAGE_A 16384
#define STAGE_SZV (STAGE_W+STAGE_A)   // 49152
#define GSMEMV (3*STAGE_SZV)          // 147456
#define EPSV 260

__global__ void __launch_bounds__(256) out_gemm_mma(
    const float* __restrict__ ob, float* __restrict__ outp)
{
  extern __shared__ __align__(128) char smg[];
  const uint32_t sbase = smem_u32(smg);
  float* eps = (float*)smg;
  const int tid  = threadIdx.x;
  const int wid  = tid >> 5;
  const int lane = tid & 31;
  const int bn = blockIdx.x * 128;
  const int bm = blockIdx.y * 256;
  const int wm = (wid & 1) * 128;
  const int wn = (wid >> 1) * 32;

  #pragma unroll
  for (int c = 0; c < 2; c++) {
    const uint32_t st = sbase + c*STAGE_SZV;
    #pragma unroll
    for (int q=0;q<8;q++){
      int s = q*256 + tid, row = s >> 3, seg = s & 7;
      cp_async16_(st + sw128_((uint32_t)(row*128 + seg*16)),
                  (const char*)g_wcat + ((size_t)(bm+row)*KCAT + c*KC)*2 + seg*16);
    }
    #pragma unroll
    for (int q=0;q<4;q++){
      int s = q*256 + tid, row = s >> 3, seg = s & 7;
      cp_async16_(st + STAGE_W + sw128_((uint32_t)(row*128 + seg*16)),
                  (const char*)g_acat + ((size_t)(bn+row)*KCAT + c*KC)*2 + seg*16);
    }
    CP_COMMIT();
  }

  float acc[8][4][4];
  #pragma unroll
  for (int i=0;i<8;i++)
    #pragma unroll
    for (int jj=0;jj<4;jj++)
      #pragma unroll
      for (int v=0;v<4;v++) acc[i][jj][v]=0.f;
  const uint32_t a_row = (uint32_t)(lane & 15);
  const uint32_t a_k16 = (uint32_t)((lane >> 4) * 16);
  const uint32_t b_row = (uint32_t)((lane & 7) + ((lane & 16) >> 1));
  const uint32_t b_k16 = (uint32_t)((lane & 8) ? 16 : 0);

  int s = 0, sw = 2;
  for (int c = 0; c < NCHUNK; c++) {
    CP_WAIT1();
    __syncthreads();
    if (c + 2 < NCHUNK) {
      const uint32_t st = sbase + sw*STAGE_SZV;
      #pragma unroll
      for (int q=0;q<8;q++){
        int sg = q*256 + tid, row = sg >> 3, seg = sg & 7;
        cp_async16_(st + sw128_((uint32_t)(row*128 + seg*16)),
                    (const char*)g_wcat + ((size_t)(bm+row)*KCAT + (c+2)*KC)*2 + seg*16);
      }
      #pragma unroll
      for (int q=0;q<4;q++){
        int sg = q*256 + tid, row = sg >> 3, seg = sg & 7;
        cp_async16_(st + STAGE_W + sw128_((uint32_t)(row*128 + seg*16)),
                    (const char*)g_acat + ((size_t)(bn+row)*KCAT + (c+2)*KC)*2 + seg*16);
      }
    }
    CP_COMMIT();
    const uint32_t wbase = sbase + s*STAGE_SZV;
    const uint32_t abase = wbase + STAGE_W;
    #pragma unroll
    for (int k = 0; k < 4; k++) {
      uint32_t af[8][4], bf[2][4];
      #pragma unroll
      for (int mt=0; mt<8; mt++)
        ldsm_x4_(af[mt], wbase + sw128_((uint32_t)((wm + mt*16 + a_row)*128) + k*32 + a_k16));
      #pragma unroll
      for (int nt2=0; nt2<2; nt2++)
        ldsm_x4_(bf[nt2], abase + sw128_((uint32_t)((wn + nt2*16 + b_row)*128) + k*32 + b_k16));
      #pragma unroll
      for (int mt=0; mt<8; mt++)
        #pragma unroll
        for (int nt=0; nt<4; nt++)
          mma16816_(acc[mt][nt], af[mt], &bf[nt>>1][(nt&1)*2]);
    }
    s  = (s  + 1 == 3) ? 0 : s  + 1;
    sw = (sw + 1 == 3) ? 0 : sw + 1;
  }
  CP_WAIT0();
  __syncthreads();
  {
    const int mq = lane >> 2;
    const int nq = (lane & 3) * 2;
    #pragma unroll
    for (int mt=0; mt<8; mt++)
      #pragma unroll
      for (int nt=0; nt<4; nt++){
        int m0 = wm + mt*16 + mq;
        int n0 = wn + nt*8 + nq;
        eps[(n0  )*EPSV + m0    ] = acc[mt][nt][0];
        eps[(n0+1)*EPSV + m0    ] = acc[mt][nt][1];
        eps[(n0  )*EPSV + m0 + 8] = acc[mt][nt][2];
        eps[(n0+1)*EPSV + m0 + 8] = acc[mt][nt][3];
      }
  }
  __syncthreads();
  {
    const int mo = (tid & 31) * 8;
    const int vg = bm + mo;
    float4 ob0 = *(const float4*)&ob[vg];
    float4 ob1 = *(const float4*)&ob[vg+4];
    #pragma unroll
    for (int it = 0; it < 16; it++) {
      int n = (tid >> 5) + it*8;
      int r = bn + n;
      if (r < NROWS) {
        const float* ep = eps + n*EPSV + mo;
        float4 v0 = *(const float4*)ep;
        float4 v1 = *(const float4*)(ep+4);
        v0.x+=ob0.x; v0.y+=ob0.y; v0.z+=ob0.z; v0.w+=ob0.w;
        v1.x+=ob1.x; v1.y+=ob1.y; v1.z+=ob1.z; v1.w+=ob1.w;
        float* op = outp + (size_t)((r & 7)*STEPS + (r >> 3))*VOCAB + vg;
        *(float4*)op     = v0;
        *(float4*)(op+4) = v1;
      }
    }
  }
}

// ============================================================
extern "C" void kernel_launch(void* const* d_in, const int* in_sizes, int n_in,
                              void* d_out, int out_size) {
  const float* thought = (const float*)d_in[0];
  const int*   captions= (const int*)  d_in[1];
  const float* emb_w   = (const float*)d_in[2];
  const float* w_ih0   = (const float*)d_in[3];
  const float* w_hh0   = (const float*)d_in[4];
  const float* b_ih0   = (const float*)d_in[5];
  const float* b_hh0   = (const float*)d_in[6];
  const float* w_ih1   = (const float*)d_in[7];
  const float* w_hh1   = (const float*)d_in[8];
  const float* b_ih1   = (const float*)d_in[9];
  const float* b_hh1   = (const float*)d_in[10];
  const float* gw1     = (const float*)d_in[11];
  const float* gb1     = (const float*)d_in[12];
  const float* gw2     = (const float*)d_in[13];
  const float* gb2     = (const float*)d_in[14];
  const float* ow      = (const float*)d_in[15];
  const float* ob      = (const float*)d_in[16];
  float* outp = (float*)d_out;

  static cudaStream_t s1 = nullptr;
  static cudaEvent_t ev0 = nullptr, ev1 = nullptr;
  if (!s1) {
    cudaStreamCreate(&s1);
    cudaEventCreateWithFlags(&ev0, cudaEventDisableTiming);
    cudaEventCreateWithFlags(&ev1, cudaEventDisableTiming);
    cudaFuncSetAttribute(out_gemm_mma, cudaFuncAttributeMaxDynamicSharedMemorySize, GSMEMV);
    cudaFuncSetAttribute(xp_gemm_mma,  cudaFuncAttributeMaxDynamicSharedMemorySize, XSMEM);
  }

  // fork: weight conversions overlap xp0 + scan0
  cudaEventRecord(ev0, 0);
  cudaStreamWaitEvent(s1, ev0, 0);
  wihcvt_kernel<<<G4, 256, 0, s1>>>(w_ih1);
  wcat_kernel<<<VOCAB, 256, 0, s1>>>(ow);
  cudaEventRecord(ev1, s1);

  xp0_kernel<<<NPAD/16, 256>>>(captions, emb_w, w_ih0, b_ih0, b_hh0);
  lstm_scan2<<<64, 256>>>(w_hh0, thought, 0);   // writes h1 split into g_acat
  cudaStreamWaitEvent(0, ev1, 0);
  {
    dim3 gx(NPAD/128, G4/128);                    // (32, 8)
    xp_gemm_mma<<<gx, 256, XSMEM>>>(b_ih1, b_hh1);
  }
  lstm_scan2<<<64, 256>>>(w_hh1, thought, 1);
  gateacat_kernel<<<512, 256>>>(gw1, gb1, gw2, gb2);
  dim3 gg(NPAD/128, VOCAB/256);                   // (32, 125)
  out_gemm_mma<<<gg, 256, GSMEMV>>>(ob, outp);
}

// round 16
// speedup vs baseline: 2.1914x; 1.2829x over previous
#include <cuda_runtime.h>
#include <cuda_bf16.h>
#include <cstdint>
#include <math.h>

#define STEPS 511
#define BATCH 8
#define HID   256
#define G4    1024
#define VOCAB 32000
#define NROWS (STEPS*BATCH)   // 4088
#define NPAD  4096
#define KCAT  768             // [hi | hi/lo split] concat K
#define NPH   4

// ---------------- scratch (no allocs allowed) ----------------
__device__ float g_xp[STEPS*BATCH*G4];                // gate-interleaved: [r][unit*4+gate]
__device__ float g_h2[STEPS*BATCH*HID];
__device__ __nv_bfloat16 g_wcat[(size_t)VOCAB*KCAT];  // 49 MB  out_w split
__device__ __nv_bfloat16 g_acat[(size_t)NPAD*KCAT];   // h1-split, then gated-h2-split
__device__ __nv_bfloat16 g_xw[(size_t)G4*KCAT];       // w_ih1 split
__device__ float g_cst[2][BATCH*HID];                 // scan phase state: c
__device__ float g_hst[2][BATCH*HID];                 // scan phase state: h

__device__ __forceinline__ float sigmoidf_(float x){ return 1.0f/(1.0f + __expf(-x)); }

__device__ __forceinline__ uint32_t smem_u32(const void* p){
  return (uint32_t)__cvta_generic_to_shared(p);
}
__device__ __forceinline__ void mbar_init_(uint32_t a, uint32_t cnt){
  asm volatile("mbarrier.init.shared.b64 [%0], %1;" :: "r"(a), "r"(cnt) : "memory");
}
__device__ __forceinline__ void mbar_expect_tx_(uint32_t a, uint32_t bytes){
  asm volatile("mbarrier.arrive.expect_tx.shared.b64 _, [%0], %1;" :: "r"(a), "r"(bytes) : "memory");
}
__device__ __forceinline__ void mbar_wait_(uint32_t a, uint32_t phase){
  asm volatile("{\n\t.reg .pred P;\n\t"
    "WL_%=:\n\t"
    "mbarrier.try_wait.parity.acquire.cta.shared::cta.b64 P, [%0], %1, 0x989680;\n\t"
    "@P bra.uni WD_%=;\n\t"
    "bra.uni WL_%=;\n\t"
    "WD_%=:\n\t}" :: "r"(a), "r"(phase) : "memory");
}
__device__ __forceinline__ void st_async_b32_(uint32_t saddr, uint32_t smbar, uint32_t rank, uint32_t v){
  asm volatile("{\n\t.reg .b32 ra, rb;\n\t"
    "mapa.shared::cluster.u32 ra, %0, %2;\n\t"
    "mapa.shared::cluster.u32 rb, %1, %2;\n\t"
    "st.async.shared::cluster.mbarrier::complete_tx::bytes.b32 [ra], %3, [rb];\n\t}"
    :: "r"(saddr), "r"(smbar), "r"(rank), "r"(v) : "memory");
}
__device__ __forceinline__ void cluster_sync_(){
  asm volatile("barrier.cluster.arrive.aligned;" ::: "memory");
  asm volatile("barrier.cluster.wait.aligned;"   ::: "memory");
}
__device__ __forceinline__ void cp_async16_(uint32_t saddr, const void* gaddr){
  asm volatile("cp.async.cg.shared.global [%0], [%1], 16;" :: "r"(saddr), "l"(gaddr) : "memory");
}
#define CP_COMMIT() asm volatile("cp.async.commit_group;" ::: "memory")
#define CP_WAIT1()  asm volatile("cp.async.wait_group 1;" ::: "memory")
#define CP_WAIT0()  asm volatile("cp.async.wait_group 0;" ::: "memory")

__device__ __forceinline__ void ldsm_x4_(uint32_t* r, uint32_t addr){
  asm volatile("ldmatrix.sync.aligned.m8n8.x4.shared.b16 {%0,%1,%2,%3}, [%4];"
    : "=r"(r[0]), "=r"(r[1]), "=r"(r[2]), "=r"(r[3]) : "r"(addr));
}
__device__ __forceinline__ void mma16816_(float* d, const uint32_t* a, const uint32_t* b){
  asm volatile("mma.sync.aligned.m16n8k16.row.col.f32.bf16.bf16.f32 "
    "{%0,%1,%2,%3}, {%4,%5,%6,%7}, {%8,%9}, {%0,%1,%2,%3};"
    : "+f"(d[0]), "+f"(d[1]), "+f"(d[2]), "+f"(d[3])
    : "r"(a[0]), "r"(a[1]), "r"(a[2]), "r"(a[3]), "r"(b[0]), "r"(b[1]));
}
static __device__ __forceinline__ uint32_t sw128_(uint32_t b){ return b ^ ((b >> 3) & 0x70u); }

// ============================================================
// Layer-0 input projection (R15 exact)
// ============================================================
__global__ void __launch_bounds__(256) xp0_kernel(
    const int* __restrict__ captions, const float* __restrict__ emb_w,
    const float* __restrict__ W, const float* __restrict__ bias1,
    const float* __restrict__ bias2)
{
  __shared__ __align__(16) float As[16][128];
  const int tid = threadIdx.x;
  const int r0  = blockIdx.x * 16;

  for (int idx = tid; idx < 16*128; idx += 256) {
    int row = idx >> 7, k = idx & 127;
    int r = r0 + row;
    float v = 0.f;
    if (r < NROWS) {
      int b = r & 7, t = r >> 3;
      v = emb_w[(size_t)captions[b*512 + t] * 128 + k];
    }
    As[row][k] = v;
  }
  __syncthreads();

  float acc[4][16];
  #pragma unroll
  for (int i=0;i<4;i++)
    #pragma unroll
    for (int r=0;r<16;r++) acc[i][r]=0.f;

  const int c0 = tid;
  for (int k0 = 0; k0 < 128; k0 += 4) {
    float4 w0 = *(const float4*)&W[(size_t)(c0      )*128 + k0];
    float4 w1 = *(const float4*)&W[(size_t)(c0+256)*128 + k0];
    float4 w2 = *(const float4*)&W[(size_t)(c0+512)*128 + k0];
    float4 w3 = *(const float4*)&W[(size_t)(c0+768)*128 + k0];
    #pragma unroll
    for (int r=0;r<16;r++) {
      float4 a4 = *(const float4*)&As[r][k0];
      acc[0][r] = fmaf(w0.x, a4.x, acc[0][r]); acc[0][r] = fmaf(w0.y, a4.y, acc[0][r]);
      acc[0][r] = fmaf(w0.z, a4.z, acc[0][r]); acc[0][r] = fmaf(w0.w, a4.w, acc[0][r]);
      acc[1][r] = fmaf(w1.x, a4.x, acc[1][r]); acc[1][r] = fmaf(w1.y, a4.y, acc[1][r]);
      acc[1][r] = fmaf(w1.z, a4.z, acc[1][r]); acc[1][r] = fmaf(w1.w, a4.w, acc[1][r]);
      acc[2][r] = fmaf(w2.x, a4.x, acc[2][r]); acc[2][r] = fmaf(w2.y, a4.y, acc[2][r]);
      acc[2][r] = fmaf(w2.z, a4.z, acc[2][r]); acc[2][r] = fmaf(w2.w, a4.w, acc[2][r]);
      acc[3][r] = fmaf(w3.x, a4.x, acc[3][r]); acc[3][r] = fmaf(w3.y, a4.y, acc[3][r]);
      acc[3][r] = fmaf(w3.z, a4.z, acc[3][r]); acc[3][r] = fmaf(w3.w, a4.w, acc[3][r]);
    }
  }
  float bb[4];
  #pragma unroll
  for (int i=0;i<4;i++) bb[i] = bias1[c0+i*256] + bias2[c0+i*256];
  #pragma unroll
  for (int r=0;r<16;r++) {
    if (r0 + r < NROWS) {
      float4 o;
      o.x = acc[0][r]+bb[0]; o.y = acc[1][r]+bb[1];
      o.z = acc[2][r]+bb[2]; o.w = acc[3][r]+bb[3];
      *(float4*)&g_xp[(size_t)(r0+r)*G4 + c0*4] = o;
    }
  }
}

// ============================================================
// LSTM scan phase [t0, t1): R15 body + gmem state save/restore
// ============================================================
__global__ __launch_bounds__(256,1) __cluster_dims__(8,1,1)
void lstm_scan2(const float* __restrict__ w_hh,
                const float* __restrict__ thought,
                int layer, int t0, int t1)
{
  __shared__ __align__(16) float h_s[2][HID];
  __shared__ __align__(8) unsigned long long mbar_sto[2];

  const int tid = threadIdx.x;
  const int b   = blockIdx.x >> 3;
  const int j   = blockIdx.x & 7;
  const int u   = tid >> 3;
  const int kp  = tid & 7;
  const int ug  = 32*j + u;

  float wreg[4][32];
  #pragma unroll
  for (int g=0; g<4; g++){
    const float* wp = w_hh + (size_t)(g*256 + ug)*HID + 32*kp;
    #pragma unroll
    for (int q=0;q<8;q++){
      float4 v = *(const float4*)(wp + 4*q);
      wreg[g][4*q+0]=v.x; wreg[g][4*q+1]=v.y; wreg[g][4*q+2]=v.z; wreg[g][4*q+3]=v.w;
    }
  }

  const uint32_t mb0 = smem_u32(&mbar_sto[0]);
  const uint32_t mb1 = smem_u32(&mbar_sto[1]);
  if (tid == 0) {
    mbar_init_(mb0, 1); mbar_init_(mb1, 1);
    mbar_expect_tx_(mb0, 1024); mbar_expect_tx_(mb1, 1024);
  }
  float c;
  if (t0 == 0) {
    h_s[0][tid] = thought[b*HID + tid];
    c = 0.f;
  } else {
    h_s[0][tid] = g_hst[layer][b*HID + tid];
    c = g_cst[layer][b*HID + ug];     // broadcast across kp lanes
  }
  __syncthreads();
  cluster_sync_();

  const uint32_t hs0 = smem_u32(&h_s[0][0]);
  const uint32_t hs1 = smem_u32(&h_s[1][0]);
  const bool owner = (kp == 0);
  const int len = t1 - t0;
  float h = 0.f;

  for (int lt = 0; lt < len; lt++) {
    const int t = t0 + lt;
    const int cur = lt & 1;

    float4 xpv = *(const float4*)&g_xp[(size_t)(t*BATCH + b)*G4 + ug*4];

    if (lt > 0) {
      mbar_wait_(cur ? mb1 : mb0, ((uint32_t)(lt-1) >> 1) & 1u);
      if (tid == 0) mbar_expect_tx_(cur ? mb1 : mb0, 1024);
    }

    float a0=0.f,a1=0.f,a2=0.f,a3=0.f;
    const float4* h4 = (const float4*)&h_s[cur][32*kp];
    #pragma unroll
    for (int q=0;q<8;q++) {
      float4 hv = h4[q];
      a0=fmaf(wreg[0][4*q+0],hv.x,a0); a0=fmaf(wreg[0][4*q+1],hv.y,a0);
      a0=fmaf(wreg[0][4*q+2],hv.z,a0); a0=fmaf(wreg[0][4*q+3],hv.w,a0);
      a1=fmaf(wreg[1][4*q+0],hv.x,a1); a1=fmaf(wreg[1][4*q+1],hv.y,a1);
      a1=fmaf(wreg[1][4*q+2],hv.z,a1); a1=fmaf(wreg[1][4*q+3],hv.w,a1);
      a2=fmaf(wreg[2][4*q+0],hv.x,a2); a2=fmaf(wreg[2][4*q+1],hv.y,a2);
      a2=fmaf(wreg[2][4*q+2],hv.z,a2); a2=fmaf(wreg[2][4*q+3],hv.w,a2);
      a3=fmaf(wreg[3][4*q+0],hv.x,a3); a3=fmaf(wreg[3][4*q+1],hv.y,a3);
      a3=fmaf(wreg[3][4*q+2],hv.z,a3); a3=fmaf(wreg[3][4*q+3],hv.w,a3);
    }
    #pragma unroll
    for (int off=4; off>=1; off>>=1) {
      a0 += __shfl_xor_sync(0xffffffffu, a0, off);
      a1 += __shfl_xor_sync(0xffffffffu, a1, off);
      a2 += __shfl_xor_sync(0xffffffffu, a2, off);
      a3 += __shfl_xor_sync(0xffffffffu, a3, off);
    }

    float gi = sigmoidf_(a0 + xpv.x);
    float gf = sigmoidf_(a1 + xpv.y);
    float gg = 2.f*sigmoidf_(2.f*(a2 + xpv.z)) - 1.f;   // tanh
    float go = sigmoidf_(a3 + xpv.w);
    c = gf*c + gi*gg;
    h = go * (2.f*sigmoidf_(2.f*c) - 1.f);
    uint32_t hv = __float_as_uint(h);

    if (lt + 1 < len) {
      uint32_t daddr = (cur ? hs0 : hs1) + (uint32_t)ug*4u;
      uint32_t dmb   = cur ? mb0 : mb1;
      st_async_b32_(daddr, dmb, (uint32_t)kp, hv);
    }

    if (owner) {
      if (layer == 0) {
        __nv_bfloat16 hi = __float2bfloat16(h);
        __nv_bfloat16 lo = __float2bfloat16(h - __bfloat162float(hi));
        __nv_bfloat16* rp = g_acat + (size_t)(t*BATCH + b)*KCAT;
        rp[ug] = hi; rp[HID + ug] = lo; rp[2*HID + ug] = hi;
      } else {
        g_h2[(size_t)(t*BATCH+b)*HID + ug] = h;
      }
    }
  }
  // phase state save (next phase restores via gmem)
  if (owner) {
    g_hst[layer][b*HID + ug] = h;
    g_cst[layer][b*HID + ug] = c;
  }
}

// ============================================================
// gate MLP fused with gated-h2 split conversion (+ block offset)
// ============================================================
__global__ void __launch_bounds__(256) gateacat_kernel(
    const float* __restrict__ gw1, const float* __restrict__ gb1,
    const float* __restrict__ gw2, const float* __restrict__ gb2,
    int blk0)
{
  __shared__ __align__(16) float Hs[8][256];
  __shared__ float wp_s[8][8];
  __shared__ float gatev[8];
  const int tid = threadIdx.x;
  const int r0  = (blk0 + blockIdx.x) * 8;

  if (r0 >= NROWS) {
    __nv_bfloat16 z = __float2bfloat16(0.f);
    #pragma unroll
    for (int row=0; row<8; row++){
      __nv_bfloat16* rp = g_acat + (size_t)(r0+row)*KCAT;
      rp[tid] = z; rp[HID+tid] = z; rp[2*HID+tid] = z;
    }
    return;
  }

  for (int idx = tid; idx < 8*256; idx += 256) {
    int row = idx >> 8, k = idx & 255;
    Hs[row][k] = g_h2[(size_t)(r0+row)*HID + k];
  }
  __syncthreads();

  float u[8];
  #pragma unroll
  for (int r=0;r<8;r++) u[r]=0.f;
  const float* wrow = gw1 + (size_t)tid*256;
  #pragma unroll 8
  for (int k0=0;k0<256;k0+=4){
    float4 w4 = *(const float4*)(wrow + k0);
    #pragma unroll
    for (int r=0;r<8;r++) {
      float4 a4 = *(const float4*)&Hs[r][k0];
      u[r] = fmaf(w4.x, a4.x, u[r]); u[r] = fmaf(w4.y, a4.y, u[r]);
      u[r] = fmaf(w4.z, a4.z, u[r]); u[r] = fmaf(w4.w, a4.w, u[r]);
    }
  }
  float g2 = gw2[tid], b1v = gb1[tid];
  float p[8];
  #pragma unroll
  for (int r=0;r<8;r++) p[r] = tanhf(u[r] + b1v) * g2;
  #pragma unroll
  for (int off=16; off>=1; off>>=1)
    #pragma unroll
    for (int r=0;r<8;r++) p[r] += __shfl_xor_sync(0xffffffffu, p[r], off);
  if ((tid & 31) == 0)
    #pragma unroll
    for (int r=0;r<8;r++) wp_s[tid>>5][r] = p[r];
  __syncthreads();
  if (tid < 8) {
    float s = 0.f;
    #pragma unroll
    for (int w=0;w<8;w++) s += wp_s[w][tid];
    gatev[tid] = sigmoidf_(s + gb2[0]);
  }
  __syncthreads();

  #pragma unroll
  for (int row=0; row<8; row++){
    float a = Hs[row][tid] * gatev[row];
    __nv_bfloat16 hi = __float2bfloat16(a);
    __nv_bfloat16 lo = __float2bfloat16(a - __bfloat162float(hi));
    __nv_bfloat16* rp = g_acat + (size_t)(r0+row)*KCAT;
    rp[tid] = hi; rp[HID+tid] = lo; rp[2*HID+tid] = hi;
  }
}

// ============================================================
// split-bf16 weight conversions (R15 exact)
// ============================================================
__global__ void __launch_bounds__(256) wcat_kernel(const float* __restrict__ ow){
  const int v = blockIdx.x, k = threadIdx.x;
  float w = ow[(size_t)v*HID + k];
  __nv_bfloat16 hi = __float2bfloat16(w);
  __nv_bfloat16 lo = __float2bfloat16(w - __bfloat162float(hi));
  __nv_bfloat16* row = g_wcat + (size_t)v*KCAT;
  row[k] = hi; row[HID + k] = hi; row[2*HID + k] = lo;
}

__global__ void __launch_bounds__(256) wihcvt_kernel(const float* __restrict__ wih){
  const int m = blockIdx.x, k = threadIdx.x;
  float w = wih[(size_t)m*HID + k];
  __nv_bfloat16 hi = __float2bfloat16(w);
  __nv_bfloat16 lo = __float2bfloat16(w - __bfloat162float(hi));
  __nv_bfloat16* row = g_xw + (size_t)m*KCAT;
  row[k] = hi; row[HID + k] = hi; row[2*HID + k] = lo;
}

// ============================================================
// 2-stage mma mainloop macro (R15 exact) — xp_gemm
// ============================================================
#define KC 64
#define NCHUNK (KCAT/KC)             // 12
#define STAGE_HALF 16384
#define STAGE_SZ   32768
#define EPS_STRIDE 132
#define XSMEM (2*STAGE_SZ + 4096)

#define MMA_MAINLOOP(WSRC, ASRC)                                                  \
  const int lrow = tid >> 1;                                                      \
  const int lseg4 = (tid & 1) * 4;                                                \
  _Pragma("unroll")                                                               \
  for (int c = 0; c < 2; c++) {                                                   \
    const uint32_t st = sbase + c*STAGE_SZ;                                       \
    const char* wg = (const char*)(WSRC) + ((size_t)(bm+lrow)*KCAT + c*KC)*2;     \
    const char* ag = (const char*)(ASRC) + ((size_t)(bn+lrow)*KCAT + c*KC)*2;     \
    _Pragma("unroll")                                                             \
    for (int q=0;q<4;q++){                                                        \
      uint32_t off = sw128_((uint32_t)(lrow*128 + (lseg4+q)*16));                 \
      cp_async16_(st + off, wg + (lseg4+q)*16);                                   \
      cp_async16_(st + STAGE_HALF + off, ag + (lseg4+q)*16);                      \
    }                                                                             \
    CP_COMMIT();                                                                  \
  }                                                                               \
  float acc[4][4][4];                                                             \
  _Pragma("unroll")                                                               \
  for (int i=0;i<4;i++)                                                           \
    _Pragma("unroll")                                                             \
    for (int jj=0;jj<4;jj++)                                                      \
      _Pragma("unroll")                                                           \
      for (int v=0;v<4;v++) acc[i][jj][v]=0.f;                                    \
  const uint32_t a_row = (uint32_t)(lane & 15);                                   \
  const uint32_t a_k16 = (uint32_t)((lane >> 4) * 16);                            \
  const uint32_t b_row = (uint32_t)((lane & 7) + ((lane & 16) >> 1));             \
  const uint32_t b_k16 = (uint32_t)((lane & 8) ? 16 : 0);                         \
  for (int c = 0; c < NCHUNK; c++) {                                              \
    CP_WAIT1();                                                                   \
    __syncthreads();                                                              \
    const uint32_t wbase = sbase + (c & 1)*STAGE_SZ;                              \
    const uint32_t abase = wbase + STAGE_HALF;                                    \
    _Pragma("unroll")                                                             \
    for (int k = 0; k < 4; k++) {                                                 \
      uint32_t af[4][4], bf[2][4];                                                \
      _Pragma("unroll")                                                           \
      for (int mt=0; mt<4; mt++)                                                  \
        ldsm_x4_(af[mt], wbase + sw128_((uint32_t)((wm + mt*16 + a_row)*128) + k*32 + a_k16)); \
      _Pragma("unroll")                                                           \
      for (int nt2=0; nt2<2; nt2++)                                               \
        ldsm_x4_(bf[nt2], abase + sw128_((uint32_t)((wn + nt2*16 + b_row)*128) + k*32 + b_k16)); \
      _Pragma("unroll")                                                           \
      for (int mt=0; mt<4; mt++)                                                  \
        _Pragma("unroll")                                                         \
        for (int nt=0; nt<4; nt++)                                                \
          mma16816_(acc[mt][nt], af[mt], &bf[nt>>1][(nt&1)*2]);                   \
    }                                                                             \
    __syncthreads();                                                              \
    if (c + 2 < NCHUNK) {                                                         \
      const uint32_t st = sbase + (c & 1)*STAGE_SZ;                               \
      const char* wg = (const char*)(WSRC) + ((size_t)(bm+lrow)*KCAT + (c+2)*KC)*2; \
      const char* ag = (const char*)(ASRC) + ((size_t)(bn+lrow)*KCAT + (c+2)*KC)*2; \
      _Pragma("unroll")                                                           \
      for (int q=0;q<4;q++){                                                      \
        uint32_t off = sw128_((uint32_t)(lrow*128 + (lseg4+q)*16));               \
        cp_async16_(st + off, wg + (lseg4+q)*16);                                 \
        cp_async16_(st + STAGE_HALF + off, ag + (lseg4+q)*16);                    \
      }                                                                           \
    }                                                                             \
    CP_COMMIT();                                                                  \
  }                                                                               \
  CP_WAIT0();                                                                     \
  __syncthreads();                                                                \
  {                                                                               \
    const int mq = lane >> 2;                                                     \
    const int nq = (lane & 3) * 2;                                                \
    _Pragma("unroll")                                                             \
    for (int mt=0; mt<4; mt++)                                                    \
      _Pragma("unroll")                                                           \
      for (int nt=0; nt<4; nt++){                                                 \
        int m0 = wm + mt*16 + mq;                                                 \
        int n0 = wn + nt*8 + nq;                                                  \
        eps[(n0  )*EPS_STRIDE + m0    ] = acc[mt][nt][0];                         \
        eps[(n0+1)*EPS_STRIDE + m0    ] = acc[mt][nt][1];                         \
        eps[(n0  )*EPS_STRIDE + m0 + 8] = acc[mt][nt][2];                         \
        eps[(n0+1)*EPS_STRIDE + m0 + 8] = acc[mt][nt][3];                         \
      }                                                                           \
  }                                                                               \
  __syncthreads();

// ============================================================
// xp1 GEMM (+ data-row block offset)
// ============================================================
__global__ void __launch_bounds__(256) xp_gemm_mma(
    const float* __restrict__ bih, const float* __restrict__ bhh, int bnoff)
{
  extern __shared__ __align__(128) char smg[];
  const uint32_t sbase = smem_u32(smg);
  float* eps = (float*)smg;
  const int tid  = threadIdx.x;
  const int wid  = tid >> 5;
  const int lane = tid & 31;
  const int bn = (blockIdx.x + bnoff) * 128;   // data rows
  const int bm = blockIdx.y * 128;             // gate rows
  const int wm = (wid & 1) * 64;
  const int wn = (wid >> 1) * 32;

  MMA_MAINLOOP(g_xw, g_acat)

  {
    const int mo = (tid & 15) * 8;
    const int mg = bm + mo;
    const int gate = bm >> 8;
    const int ub = mg & 255;
    float bb[8];
    #pragma unroll
    for (int q=0;q<8;q++) bb[q] = bih[mg+q] + bhh[mg+q];
    #pragma unroll
    for (int it = 0; it < 8; it++) {
      int n = (tid >> 4) + it*16;
      int r = bn + n;
      if (r < NROWS) {
        const float* ep = eps + n*EPS_STRIDE + mo;
        float* op = g_xp + (size_t)r*G4 + ub*4 + gate;
        #pragma unroll
        for (int q=0;q<8;q++)
          op[q*4] = ep[q] + bb[q];
      }
    }
  }
}

// ============================================================
// vocab GEMM: 256x128 tile, 3-stage ring (+ data-row offset)
// ============================================================
#define STAGE_W 32768
#define STAGE_A 16384
#define STAGE_SZV (STAGE_W+STAGE_A)   // 49152
#define GSMEMV (3*STAGE_SZV)          // 147456
#define EPSV 260

__global__ void __launch_bounds__(256) out_gemm_mma(
    const float* __restrict__ ob, float* __restrict__ outp, int bnoff)
{
  extern __shared__ __align__(128) char smg[];
  const uint32_t sbase = smem_u32(smg);
  float* eps = (float*)smg;
  const int tid  = threadIdx.x;
  const int wid  = tid >> 5;
  const int lane = tid & 31;
  const int bn = (blockIdx.x + bnoff) * 128;
  const int bm = blockIdx.y * 256;
  const int wm = (wid & 1) * 128;
  const int wn = (wid >> 1) * 32;

  #pragma unroll
  for (int c = 0; c < 2; c++) {
    const uint32_t st = sbase + c*STAGE_SZV;
    #pragma unroll
    for (int q=0;q<8;q++){
      int s = q*256 + tid, row = s >> 3, seg = s & 7;
      cp_async16_(st + sw128_((uint32_t)(row*128 + seg*16)),
                  (const char*)g_wcat + ((size_t)(bm+row)*KCAT + c*KC)*2 + seg*16);
    }
    #pragma unroll
    for (int q=0;q<4;q++){
      int s = q*256 + tid, row = s >> 3, seg = s & 7;
      cp_async16_(st + STAGE_W + sw128_((uint32_t)(row*128 + seg*16)),
                  (const char*)g_acat + ((size_t)(bn+row)*KCAT + c*KC)*2 + seg*16);
    }
    CP_COMMIT();
  }

  float acc[8][4][4];
  #pragma unroll
  for (int i=0;i<8;i++)
    #pragma unroll
    for (int jj=0;jj<4;jj++)
      #pragma unroll
      for (int v=0;v<4;v++) acc[i][jj][v]=0.f;
  const uint32_t a_row = (uint32_t)(lane & 15);
  const uint32_t a_k16 = (uint32_t)((lane >> 4) * 16);
  const uint32_t b_row = (uint32_t)((lane & 7) + ((lane & 16) >> 1));
  const uint32_t b_k16 = (uint32_t)((lane & 8) ? 16 : 0);

  int s = 0, sw = 2;
  for (int c = 0; c < NCHUNK; c++) {
    CP_WAIT1();
    __syncthreads();
    if (c + 2 < NCHUNK) {
      const uint32_t st = sbase + sw*STAGE_SZV;
      #pragma unroll
      for (int q=0;q<8;q++){
        int sg = q*256 + tid, row = sg >> 3, seg = sg & 7;
        cp_async16_(st + sw128_((uint32_t)(row*128 + seg*16)),
                    (const char*)g_wcat + ((size_t)(bm+row)*KCAT + (c+2)*KC)*2 + seg*16);
      }
      #pragma unroll
      for (int q=0;q<4;q++){
        int sg = q*256 + tid, row = sg >> 3, seg = sg & 7;
        cp_async16_(st + STAGE_W + sw128_((uint32_t)(row*128 + seg*16)),
                    (const char*)g_acat + ((size_t)(bn+row)*KCAT + (c+2)*KC)*2 + seg*16);
      }
    }
    CP_COMMIT();
    const uint32_t wbase = sbase + s*STAGE_SZV;
    const uint32_t abase = wbase + STAGE_W;
    #pragma unroll
    for (int k = 0; k < 4; k++) {
      uint32_t af[8][4], bf[2][4];
      #pragma unroll
      for (int mt=0; mt<8; mt++)
        ldsm_x4_(af[mt], wbase + sw128_((uint32_t)((wm + mt*16 + a_row)*128) + k*32 + a_k16));
      #pragma unroll
      for (int nt2=0; nt2<2; nt2++)
        ldsm_x4_(bf[nt2], abase + sw128_((uint32_t)((wn + nt2*16 + b_row)*128) + k*32 + b_k16));
      #pragma unroll
      for (int mt=0; mt<8; mt++)
        #pragma unroll
        for (int nt=0; nt<4; nt++)
          mma16816_(acc[mt][nt], af[mt], &bf[nt>>1][(nt&1)*2]);
    }
    s  = (s  + 1 == 3) ? 0 : s  + 1;
    sw = (sw + 1 == 3) ? 0 : sw + 1;
  }
  CP_WAIT0();
  __syncthreads();
  {
    const int mq = lane >> 2;
    const int nq = (lane & 3) * 2;
    #pragma unroll
    for (int mt=0; mt<8; mt++)
      #pragma unroll
      for (int nt=0; nt<4; nt++){
        int m0 = wm + mt*16 + mq;
        int n0 = wn + nt*8 + nq;
        eps[(n0  )*EPSV + m0    ] = acc[mt][nt][0];
        eps[(n0+1)*EPSV + m0    ] = acc[mt][nt][1];
        eps[(n0  )*EPSV + m0 + 8] = acc[mt][nt][2];
        eps[(n0+1)*EPSV + m0 + 8] = acc[mt][nt][3];
      }
  }
  __syncthreads();
  {
    const int mo = (tid & 31) * 8;
    const int vg = bm + mo;
    float4 ob0 = *(const float4*)&ob[vg];
    float4 ob1 = *(const float4*)&ob[vg+4];
    #pragma unroll
    for (int it = 0; it < 16; it++) {
      int n = (tid >> 5) + it*8;
      int r = bn + n;
      if (r < NROWS) {
        const float* ep = eps + n*EPSV + mo;
        float4 v0 = *(const float4*)ep;
        float4 v1 = *(const float4*)(ep+4);
        v0.x+=ob0.x; v0.y+=ob0.y; v0.z+=ob0.z; v0.w+=ob0.w;
        v1.x+=ob1.x; v1.y+=ob1.y; v1.z+=ob1.z; v1.w+=ob1.w;
        float* op = outp + (size_t)((r & 7)*STEPS + (r >> 3))*VOCAB + vg;
        *(float4*)op     = v0;
        *(float4*)(op+4) = v1;
      }
    }
  }
}

// ============================================================
extern "C" void kernel_launch(void* const* d_in, const int* in_sizes, int n_in,
                              void* d_out, int out_size) {
  const float* thought = (const float*)d_in[0];
  const int*   captions= (const int*)  d_in[1];
  const float* emb_w   = (const float*)d_in[2];
  const float* w_ih0   = (const float*)d_in[3];
  const float* w_hh0   = (const float*)d_in[4];
  const float* b_ih0   = (const float*)d_in[5];
  const float* b_hh0   = (const float*)d_in[6];
  const float* w_ih1   = (const float*)d_in[7];
  const float* w_hh1   = (const float*)d_in[8];
  const float* b_ih1   = (const float*)d_in[9];
  const float* b_hh1   = (const float*)d_in[10];
  const float* gw1     = (const float*)d_in[11];
  const float* gb1     = (const float*)d_in[12];
  const float* gw2     = (const float*)d_in[13];
  const float* gb2     = (const float*)d_in[14];
  const float* ow      = (const float*)d_in[15];
  const float* ob      = (const float*)d_in[16];
  float* outp = (float*)d_out;

  static cudaStream_t sB = nullptr, sC = nullptr, s1 = nullptr;
  static cudaEvent_t ev0 = nullptr, evw1 = nullptr, evW = nullptr, evC = nullptr;
  static cudaEvent_t evS0[NPH], evS1[NPH];
  if (!sB) {
    int lo, hi;
    cudaDeviceGetStreamPriorityRange(&lo, &hi);
    cudaStreamCreateWithPriority(&sB, cudaStreamNonBlocking, hi);
    cudaStreamCreateWithPriority(&sC, cudaStreamNonBlocking, lo);
    cudaStreamCreateWithPriority(&s1, cudaStreamNonBlocking, lo);
    cudaEventCreateWithFlags(&ev0,  cudaEventDisableTiming);
    cudaEventCreateWithFlags(&evw1, cudaEventDisableTiming);
    cudaEventCreateWithFlags(&evW,  cudaEventDisableTiming);
    cudaEventCreateWithFlags(&evC,  cudaEventDisableTiming);
    for (int p=0;p<NPH;p++){
      cudaEventCreateWithFlags(&evS0[p], cudaEventDisableTiming);
      cudaEventCreateWithFlags(&evS1[p], cudaEventDisableTiming);
    }
    cudaFuncSetAttribute(out_gemm_mma, cudaFuncAttributeMaxDynamicSharedMemorySize, GSMEMV);
    cudaFuncSetAttribute(xp_gemm_mma,  cudaFuncAttributeMaxDynamicSharedMemorySize, XSMEM);
  }
  static const int T0[NPH] = {0, 128, 256, 384};
  static const int T1[NPH] = {128, 256, 384, 511};

  // fork: weight conversions
  cudaEventRecord(ev0, 0);
  cudaStreamWaitEvent(s1, ev0, 0);
  wihcvt_kernel<<<G4, 256, 0, s1>>>(w_ih1);
  cudaEventRecord(evw1, s1);
  wcat_kernel<<<VOCAB, 256, 0, s1>>>(ow);
  cudaEventRecord(evW, s1);

  // main: xp0 then scan0 phases back-to-back
  xp0_kernel<<<NPAD/16, 256>>>(captions, emb_w, w_ih0, b_ih0, b_hh0);
  for (int p = 0; p < NPH; p++) {
    lstm_scan2<<<64, 256>>>(w_hh0, thought, 0, T0[p], T1[p]);
    cudaEventRecord(evS0[p], 0);
  }

  // sB: per phase, xp1 GEMM chunk then scan1 phase
  cudaStreamWaitEvent(sB, evw1, 0);
  for (int p = 0; p < NPH; p++) {
    cudaStreamWaitEvent(sB, evS0[p], 0);
    dim3 gx(8, G4/128);
    xp_gemm_mma<<<gx, 256, XSMEM, sB>>>(b_ih1, b_hh1, p*8);
    lstm_scan2<<<64, 256, 0, sB>>>(w_hh1, thought, 1, T0[p], T1[p]);
    cudaEventRecord(evS1[p], sB);
  }

  // sC: per phase, gate+acat then vocab GEMM chunk
  cudaStreamWaitEvent(sC, evW, 0);
  for (int p = 0; p < NPH; p++) {
    cudaStreamWaitEvent(sC, evS1[p], 0);
    gateacat_kernel<<<128, 256, 0, sC>>>(gw1, gb1, gw2, gb2, p*128);
    dim3 gg(8, VOCAB/256);
    out_gemm_mma<<<gg, 256, GSMEMV, sC>>>(ob, outp, p*8);
  }
  cudaEventRecord(evC, sC);
  cudaStreamWaitEvent(0, evC, 0);
}